// round 2
// baseline (speedup 1.0000x reference)
#include <cuda_runtime.h>
#include <math.h>

#define BB 8
#define CC 256
#define CI 128
#define HH 64
#define WD 64
#define NPIX 4096   // 64*64
#define NPOOL 1024  // 32*32
#define BN_EPS 1e-5f

// ---------------- scratch (single __device__ global, no allocations) ----------
#define SZ_PROJ ((size_t)BB * CI * NPIX)    // 4,194,304 floats
#define SZ_POOL ((size_t)BB * CI * NPOOL)   // 1,048,576
#define SZ_F    ((size_t)BB * NPIX * NPOOL) // 33,554,432

#define OFF_THETA ((size_t)0)              // [b][ci][n]
#define OFF_PHIF  (SZ_PROJ)                // [b][ci][n] full-res phi conv
#define OFF_GF    (2 * SZ_PROJ)            // [b][ci][n] full-res g conv
#define OFF_PHIP  (3 * SZ_PROJ)            // [b][ci][m] pooled phi
#define OFF_GPT   (OFF_PHIP + SZ_POOL)     // [b][m][ci] pooled g (transposed)
#define OFF_F     (OFF_GPT + SZ_POOL)      // [b][n][m]
#define OFF_Y     (OFF_F + SZ_F)           // [b][n][ci]
#define SCRATCH_SZ (OFF_Y + SZ_PROJ)       // 52,428,800 floats (~210 MB)

__device__ float d_scratch[SCRATCH_SZ];

// ---------------- packed fp32 helpers (Blackwell FFMA2) -----------------------
__device__ __forceinline__ void ffma2(unsigned long long& d,
                                      unsigned long long a,
                                      unsigned long long b)
{
    asm("fma.rn.f32x2 %0, %1, %2, %0;" : "+l"(d) : "l"(a), "l"(b));
}
__device__ __forceinline__ unsigned long long splat2(float x)
{
    unsigned long long d;
    unsigned int u = __float_as_uint(x);
    asm("mov.b64 %0, {%1, %1};" : "=l"(d) : "r"(u));
    return d;
}
__device__ __forceinline__ void unpack2(unsigned long long v, float& lo, float& hi)
{
    unsigned int a, b;
    asm("mov.b64 {%0, %1}, %2;" : "=r"(a), "=r"(b) : "l"(v));
    lo = __uint_as_float(a);
    hi = __uint_as_float(b);
}

// ---------------- shared 64x64x16 fp32x2 micro-kernel --------------------------
// acc[p][j]: row-pair p (rows 4*ty+2p, 4*ty+2p+1), col 4*tx+j, packed (lo=even row).
__device__ __forceinline__ void mm16(const float (*As)[68], const float (*Bs)[68],
                                     unsigned long long acc[2][4], int tx, int ty)
{
#pragma unroll
    for (int k = 0; k < 16; ++k) {
        const ulonglong2 av = *(const ulonglong2*)&As[k][ty << 2]; // rows pair-packed
        const float4 b = *(const float4*)&Bs[k][tx << 2];
        unsigned long long b0 = splat2(b.x), b1 = splat2(b.y),
                           b2 = splat2(b.z), b3 = splat2(b.w);
        ffma2(acc[0][0], av.x, b0); ffma2(acc[0][1], av.x, b1);
        ffma2(acc[0][2], av.x, b2); ffma2(acc[0][3], av.x, b3);
        ffma2(acc[1][0], av.y, b0); ffma2(acc[1][1], av.y, b1);
        ffma2(acc[1][2], av.y, b2); ffma2(acc[1][3], av.y, b3);
    }
}

// Unpack acc into r[row 0..3][col 0..3]
__device__ __forceinline__ void unpack_acc(const unsigned long long acc[2][4],
                                           float r[4][4])
{
#pragma unroll
    for (int p = 0; p < 2; ++p)
#pragma unroll
        for (int j = 0; j < 4; ++j)
            unpack2(acc[p][j], r[2 * p][j], r[2 * p + 1][j]);
}

// ---------------- 1) projection GEMM: out[b][m][n] = sum_k w[m][k]*x[b][k][n] + bias[m]
// M=CI, N=NPIX, K=CC. grid (NPIX/64, CI/64, BB), block 256.
__global__ __launch_bounds__(256) void proj_kernel(
    const float* __restrict__ x, const float* __restrict__ w,
    const float* __restrict__ bias, int sel)
{
    float* out = d_scratch + (size_t)sel * SZ_PROJ;
    const int b  = blockIdx.z;
    const int n0 = blockIdx.x * 64;
    const int m0 = blockIdx.y * 64;
    const float* X = x + (size_t)b * CC * NPIX;
    float* O = out + (size_t)b * CI * NPIX;

    __shared__ float As[16][68];
    __shared__ float Bs[16][68];

    const int tid = threadIdx.x;
    const int tx = tid & 15, ty = tid >> 4;
    const int am = tid >> 2, ak = (tid & 3) << 2;   // A transpose-loader
    const int bk = tid >> 4, bn = (tid & 15) << 2;  // B direct loader

    unsigned long long acc[2][4] = {};
    for (int k0 = 0; k0 < CC; k0 += 16) {
        float4 av = *(const float4*)(w + (size_t)(m0 + am) * CC + k0 + ak);
        As[ak + 0][am] = av.x; As[ak + 1][am] = av.y;
        As[ak + 2][am] = av.z; As[ak + 3][am] = av.w;
        *(float4*)&Bs[bk][bn] = *(const float4*)(X + (size_t)(k0 + bk) * NPIX + n0 + bn);
        __syncthreads();
        mm16(As, Bs, acc, tx, ty);
        __syncthreads();
    }
    float r[4][4];
    unpack_acc(acc, r);
#pragma unroll
    for (int i = 0; i < 4; ++i) {
        int m = m0 + (ty << 2) + i;
        float bv = bias[m];
        float4 o = make_float4(r[i][0] + bv, r[i][1] + bv, r[i][2] + bv, r[i][3] + bv);
        *(float4*)(O + (size_t)m * NPIX + n0 + (tx << 2)) = o;
    }
}

// ---------------- 2) 2x2 max pool: phiP[b][ci][m], gPt[b][m][ci] ---------------
__global__ __launch_bounds__(256) void pool_kernel()
{
    int idx = blockIdx.x * blockDim.x + threadIdx.x;   // (b,ci,m), m fastest
    if (idx >= (int)(BB * CI * NPOOL)) return;
    int m  = idx & (NPOOL - 1);
    int ci = (idx >> 10) & (CI - 1);
    int b  = idx >> 17;
    int ph = m >> 5, pw = m & 31;
    size_t base = ((size_t)b * CI + ci) * NPIX + (size_t)(2 * ph) * WD + 2 * pw;

    const float* pf = d_scratch + OFF_PHIF;
    float p = fmaxf(fmaxf(pf[base], pf[base + 1]),
                    fmaxf(pf[base + WD], pf[base + WD + 1]));
    d_scratch[OFF_PHIP + (size_t)idx] = p;

    const float* gf = d_scratch + OFF_GF;
    float g = fmaxf(fmaxf(gf[base], gf[base + 1]),
                    fmaxf(gf[base + WD], gf[base + WD + 1]));
    d_scratch[OFF_GPT + ((size_t)b * NPOOL + m) * CI + ci] = g;
}

// ---------------- 3) f GEMM (TN): f[b][n][m] = sum_k theta[b][k][n]*phiP[b][k][m]
// M=NPIX(n), N=NPOOL(m), K=CI. grid (NPOOL/64, NPIX/64, BB)
__global__ __launch_bounds__(256) void gemm_f_kernel()
{
    const int b  = blockIdx.z;
    const int c0 = blockIdx.x * 64;
    const int r0 = blockIdx.y * 64;
    const float* A = d_scratch + OFF_THETA + (size_t)b * CI * NPIX;
    const float* Bm = d_scratch + OFF_PHIP + (size_t)b * CI * NPOOL;
    float* F = d_scratch + OFF_F + (size_t)b * NPIX * NPOOL;

    __shared__ float As[16][68];
    __shared__ float Bs[16][68];
    const int tid = threadIdx.x;
    const int tx = tid & 15, ty = tid >> 4;
    const int lk = tid >> 4, lc = (tid & 15) << 2;

    unsigned long long acc[2][4] = {};
    for (int k0 = 0; k0 < CI; k0 += 16) {
        *(float4*)&As[lk][lc] = *(const float4*)(A  + (size_t)(k0 + lk) * NPIX  + r0 + lc);
        *(float4*)&Bs[lk][lc] = *(const float4*)(Bm + (size_t)(k0 + lk) * NPOOL + c0 + lc);
        __syncthreads();
        mm16(As, Bs, acc, tx, ty);
        __syncthreads();
    }
    float r[4][4];
    unpack_acc(acc, r);
#pragma unroll
    for (int i = 0; i < 4; ++i) {
        *(float4*)(F + (size_t)(r0 + (ty << 2) + i) * NPOOL + c0 + (tx << 2)) =
            make_float4(r[i][0], r[i][1], r[i][2], r[i][3]);
    }
}

// ---------------- 4) row softmax over m (1024), block per row -----------------
__global__ __launch_bounds__(256) void softmax_kernel()
{
    __shared__ float rmax[8], rsum[8], bval[2];
    size_t row = blockIdx.x;
    float4* p = (float4*)(d_scratch + OFF_F + row * (size_t)NPOOL);
    const int tid = threadIdx.x;
    const int lane = tid & 31, wid = tid >> 5;

    float4 v = p[tid];
    float mx = fmaxf(fmaxf(v.x, v.y), fmaxf(v.z, v.w));
#pragma unroll
    for (int o = 16; o; o >>= 1) mx = fmaxf(mx, __shfl_xor_sync(0xffffffffu, mx, o));
    if (lane == 0) rmax[wid] = mx;
    __syncthreads();
    if (tid == 0) {
        float m = rmax[0];
#pragma unroll
        for (int i = 1; i < 8; ++i) m = fmaxf(m, rmax[i]);
        bval[0] = m;
    }
    __syncthreads();
    float M = bval[0];
    v.x = expf(v.x - M); v.y = expf(v.y - M);
    v.z = expf(v.z - M); v.w = expf(v.w - M);
    float s = v.x + v.y + v.z + v.w;
#pragma unroll
    for (int o = 16; o; o >>= 1) s += __shfl_xor_sync(0xffffffffu, s, o);
    if (lane == 0) rsum[wid] = s;
    __syncthreads();
    if (tid == 0) {
        float t = 0.f;
#pragma unroll
        for (int i = 0; i < 8; ++i) t += rsum[i];
        bval[1] = 1.f / t;
    }
    __syncthreads();
    float r = bval[1];
    v.x *= r; v.y *= r; v.z *= r; v.w *= r;
    p[tid] = v;
}

// ---------------- 5) y GEMM (NN): y[b][n][c] = sum_k f[b][n][k]*gPt[b][k][c]
// M=NPIX, N=CI, K=NPOOL. grid (CI/64, NPIX/64, BB)
__global__ __launch_bounds__(256) void gemm_y_kernel()
{
    const int b  = blockIdx.z;
    const int c0 = blockIdx.x * 64;
    const int r0 = blockIdx.y * 64;
    const float* F = d_scratch + OFF_F   + (size_t)b * NPIX * NPOOL;
    const float* G = d_scratch + OFF_GPT + (size_t)b * NPOOL * CI;
    float* Y = d_scratch + OFF_Y + (size_t)b * NPIX * CI;

    __shared__ float As[16][68];
    __shared__ float Bs[16][68];
    const int tid = threadIdx.x;
    const int tx = tid & 15, ty = tid >> 4;
    const int am = tid >> 2, ak = (tid & 3) << 2;
    const int bk = tid >> 4, bn = (tid & 15) << 2;

    unsigned long long acc[2][4] = {};
    for (int k0 = 0; k0 < NPOOL; k0 += 16) {
        float4 av = *(const float4*)(F + (size_t)(r0 + am) * NPOOL + k0 + ak);
        As[ak + 0][am] = av.x; As[ak + 1][am] = av.y;
        As[ak + 2][am] = av.z; As[ak + 3][am] = av.w;
        *(float4*)&Bs[bk][bn] = *(const float4*)(G + (size_t)(k0 + bk) * CI + c0 + bn);
        __syncthreads();
        mm16(As, Bs, acc, tx, ty);
        __syncthreads();
    }
    float r[4][4];
    unpack_acc(acc, r);
#pragma unroll
    for (int i = 0; i < 4; ++i) {
        *(float4*)(Y + (size_t)(r0 + (ty << 2) + i) * CI + c0 + (tx << 2)) =
            make_float4(r[i][0], r[i][1], r[i][2], r[i][3]);
    }
}

// ---------------- 6) out GEMM + BN + residual ---------------------------------
// o[b][c][n] = ((sum_k Ww[c][k]*y[b][n][k]) + Wb[c] - mean[c])*inv[c] + beta[c] + x[b][c][n]
// M=CC(c), N=NPIX(n), K=CI. grid (NPIX/64, CC/64, BB)
__global__ __launch_bounds__(256) void gemm_out_kernel(
    const float* __restrict__ Ww, const float* __restrict__ Wb,
    const float* __restrict__ gamma, const float* __restrict__ beta,
    const float* __restrict__ mean, const float* __restrict__ var,
    const float* __restrict__ x, float* __restrict__ out)
{
    const int b  = blockIdx.z;
    const int n0 = blockIdx.x * 64;
    const int m0 = blockIdx.y * 64;
    const float* Y = d_scratch + OFF_Y + (size_t)b * NPIX * CI;

    __shared__ float As[16][68];
    __shared__ float Bs[16][68];
    const int tid = threadIdx.x;
    const int tx = tid & 15, ty = tid >> 4;
    const int am = tid >> 2, ak = (tid & 3) << 2;  // reused for both transpose loaders

    unsigned long long acc[2][4] = {};
    for (int k0 = 0; k0 < CI; k0 += 16) {
        float4 av = *(const float4*)(Ww + (size_t)(m0 + am) * CI + k0 + ak);
        As[ak + 0][am] = av.x; As[ak + 1][am] = av.y;
        As[ak + 2][am] = av.z; As[ak + 3][am] = av.w;
        float4 bv = *(const float4*)(Y + (size_t)(n0 + am) * CI + k0 + ak);
        Bs[ak + 0][am] = bv.x; Bs[ak + 1][am] = bv.y;
        Bs[ak + 2][am] = bv.z; Bs[ak + 3][am] = bv.w;
        __syncthreads();
        mm16(As, Bs, acc, tx, ty);
        __syncthreads();
    }
    float r[4][4];
    unpack_acc(acc, r);
#pragma unroll
    for (int i = 0; i < 4; ++i) {
        int c = m0 + (ty << 2) + i;
        float inv = gamma[c] / sqrtf(var[c] + BN_EPS);
        float sh = (Wb[c] - mean[c]) * inv + beta[c];
        size_t off = ((size_t)b * CC + c) * NPIX + n0 + (tx << 2);
        float4 xv = *(const float4*)(x + off);
        float4 o = make_float4(r[i][0] * inv + sh + xv.x,
                               r[i][1] * inv + sh + xv.y,
                               r[i][2] * inv + sh + xv.z,
                               r[i][3] * inv + sh + xv.w);
        *(float4*)(out + off) = o;
    }
}

// ---------------- launch -------------------------------------------------------
extern "C" void kernel_launch(void* const* d_in, const int* in_sizes, int n_in,
                              void* d_out, int out_size)
{
    const float* x    = (const float*)d_in[0];
    const float* g_w  = (const float*)d_in[1];
    const float* g_b  = (const float*)d_in[2];
    const float* th_w = (const float*)d_in[3];
    const float* th_b = (const float*)d_in[4];
    const float* ph_w = (const float*)d_in[5];
    const float* ph_b = (const float*)d_in[6];
    const float* W_w  = (const float*)d_in[7];
    const float* W_b  = (const float*)d_in[8];
    const float* gam  = (const float*)d_in[9];
    const float* bet  = (const float*)d_in[10];
    const float* mea  = (const float*)d_in[11];
    const float* var  = (const float*)d_in[12];
    float* out = (float*)d_out;

    dim3 blk(256);
    proj_kernel<<<dim3(NPIX / 64, CI / 64, BB), blk>>>(x, th_w, th_b, 0); // theta
    proj_kernel<<<dim3(NPIX / 64, CI / 64, BB), blk>>>(x, ph_w, ph_b, 1); // phi (full)
    proj_kernel<<<dim3(NPIX / 64, CI / 64, BB), blk>>>(x, g_w,  g_b,  2); // g (full)
    pool_kernel<<<(BB * CI * NPOOL) / 256, blk>>>();
    gemm_f_kernel<<<dim3(NPOOL / 64, NPIX / 64, BB), blk>>>();
    softmax_kernel<<<BB * NPIX, blk>>>();
    gemm_y_kernel<<<dim3(CI / 64, NPIX / 64, BB), blk>>>();
    gemm_out_kernel<<<dim3(NPIX / 64, CC / 64, BB), blk>>>(W_w, W_b, gam, bet, mea, var, x, out);
}

// round 4
// speedup vs baseline: 1.7023x; 1.7023x over previous
#include <cuda_runtime.h>
#include <cuda_bf16.h>
#include <math.h>
#include <stdint.h>

#define BB 8
#define CC 256
#define CI 128
#define NPIX 4096
#define NPOOL 1024
#define WD 64
#define BN_EPS 1e-5f

// ---------------- scratch (__device__ globals, no allocations) ----------------
__device__ __align__(16) __nv_bfloat16 d_x3 [(size_t)BB * NPIX * (3 * CC)]; // A of proj: [b][n][hi|lo|hi over c]
__device__ __align__(16) __nv_bfloat16 d_w3t[(size_t)CI * 3 * CC];          // B of proj theta: [ci][hi|hi|lo]
__device__ __align__(16) __nv_bfloat16 d_w3p[(size_t)CI * 3 * CC];
__device__ __align__(16) __nv_bfloat16 d_w3g[(size_t)CI * 3 * CC];
__device__ __align__(16) __nv_bfloat16 d_Ww3[(size_t)CC * 3 * CI];          // A of out: [c][hi|lo|hi]
__device__ __align__(16) __nv_bfloat16 d_th3[(size_t)BB * NPIX * (3 * CI)]; // A of f: [b][n][hi|lo|hi]
__device__ __align__(16) float         d_phiF[(size_t)BB * NPIX * CI];      // [b][n][ci]
__device__ __align__(16) float         d_gF  [(size_t)BB * NPIX * CI];
__device__ __align__(16) __nv_bfloat16 d_phiP3[(size_t)BB * NPOOL * (3 * CI)]; // B of f: [m][hi|hi|lo]
__device__ __align__(16) __nv_bfloat16 d_gP3 [(size_t)BB * CI * (3 * NPOOL)];  // B of y: [ci][hi|hi|lo]
__device__ __align__(16) float         d_f   [(size_t)BB * NPIX * NPOOL];   // [b][n][m]
__device__ __align__(16) __nv_bfloat16 d_P3  [(size_t)BB * NPIX * (3 * NPOOL)]; // A of y: [n][hi|lo|hi]
__device__ __align__(16) __nv_bfloat16 d_y3  [(size_t)BB * NPIX * (3 * CI)];    // B of out: [n][hi|hi|lo]

// ---------------- helpers -------------------------------------------------------
__device__ __forceinline__ uint32_t smem_u32(const void* p) {
    uint32_t a;
    asm("{ .reg .u64 t; cvta.to.shared.u64 t, %1; cvt.u32.u64 %0, t; }" : "=r"(a) : "l"(p));
    return a;
}
__device__ __forceinline__ uint32_t pack_bf2(__nv_bfloat16 a, __nv_bfloat16 b) {
    __nv_bfloat162 h(a, b);
    return *(uint32_t*)&h;
}
#define CP16(dst, src) asm volatile("cp.async.ca.shared.global [%0], [%1], 16;" :: "r"(dst), "l"(src))
#define CP_COMMIT()    asm volatile("cp.async.commit_group;" ::: "memory")
#define CP_WAIT1()     asm volatile("cp.async.wait_group 1;" ::: "memory")
#define CP_WAIT0()     asm volatile("cp.async.wait_group 0;" ::: "memory")

__device__ __forceinline__ void ldsm_x4(uint32_t* r, uint32_t addr) {
    asm volatile("ldmatrix.sync.aligned.m8n8.x4.shared.b16 {%0,%1,%2,%3}, [%4];"
                 : "=r"(r[0]), "=r"(r[1]), "=r"(r[2]), "=r"(r[3]) : "r"(addr));
}
__device__ __forceinline__ void ldsm_x2(uint32_t* r, uint32_t addr) {
    asm volatile("ldmatrix.sync.aligned.m8n8.x2.shared.b16 {%0,%1}, [%2];"
                 : "=r"(r[0]), "=r"(r[1]) : "r"(addr));
}
__device__ __forceinline__ void mma16816(float* c, const uint32_t* a, const uint32_t* b) {
    asm volatile("mma.sync.aligned.m16n8k16.row.col.f32.bf16.bf16.f32 "
                 "{%0,%1,%2,%3}, {%4,%5,%6,%7}, {%8,%9}, {%0,%1,%2,%3};"
                 : "+f"(c[0]), "+f"(c[1]), "+f"(c[2]), "+f"(c[3])
                 : "r"(a[0]), "r"(a[1]), "r"(a[2]), "r"(a[3]), "r"(b[0]), "r"(b[1]));
}

// smem: 2 stages x (A 128x40 bf16 + B 128x40 bf16). row pitch 80B (conflict-free ldmatrix)
#define STG_BYTES 20480
#define SB_OFF    10240

// ---------------- generic warp-mma GEMM, 128x128 tile, K' = 32*nchunks ----------
// A [rows][ldK], B [cols][ldK] bf16; D = A * B^T  (fp32 accum)
// MODE 0: fp32 out + bias[col]      MODE 1: bf16 trio out (hi|lo|hi) + bias[col]
// MODE 2: fp32 out, no bias         MODE 3: bf16 trio out (hi|hi|lo)
// MODE 4: fp32 out + BN(row) + residual (p0=Wb p1=gamma p2=beta p3=mean p4=var p5=x)
template <int MODE>
__global__ __launch_bounds__(256) void mma_gemm(
    const __nv_bfloat16* __restrict__ A, const __nv_bfloat16* __restrict__ B,
    size_t sAb, size_t sBb, int ldK, int nchunks,
    float* OF, __nv_bfloat16* O3, size_t sOb, int ldO,
    const float* __restrict__ p0, const float* __restrict__ p1,
    const float* __restrict__ p2, const float* __restrict__ p3,
    const float* __restrict__ p4, const float* __restrict__ p5)
{
    __shared__ __align__(16) char sm[2 * STG_BYTES];
    const uint32_t smb = smem_u32(sm);
    const int tid = threadIdx.x;
    const int wid = tid >> 5, lid = tid & 31;
    const int b = blockIdx.z;
    const int row0 = blockIdx.y * 128, col0 = blockIdx.x * 128;
    const int m_base = (wid & 1) * 64;        // warp tile 64x32
    const int n_base = (wid >> 1) * 32;

    const __nv_bfloat16* At = A + sAb * b + (size_t)row0 * ldK;
    const __nv_bfloat16* Bt = B + sBb * b + (size_t)col0 * ldK;

    // loader: 512 uint4 per operand per chunk, 2 per thread
    const int r0i = tid >> 2, s0 = (tid & 3);          // idx = tid
    const int r1i = (tid + 256) >> 2, s1 = s0;         // idx = tid+256
    const uint32_t d0 = (uint32_t)(r0i * 80 + s0 * 16);
    const uint32_t d1 = (uint32_t)(r1i * 80 + s1 * 16);

    // ldmatrix lane addresses
    const uint32_t aOff = (uint32_t)((m_base + (lid & 15)) * 80 + (lid >> 4) * 16);
    const uint32_t bOff = (uint32_t)((n_base + (lid & 7)) * 80 + ((lid >> 3) & 1) * 16);

    float acc[4][4][4];
#pragma unroll
    for (int i = 0; i < 4; ++i)
#pragma unroll
        for (int j = 0; j < 4; ++j)
#pragma unroll
            for (int q = 0; q < 4; ++q) acc[i][j][q] = 0.f;

    auto issue = [&](int ch) {
        const uint32_t sa = smb + (uint32_t)(ch & 1) * STG_BYTES;
        const uint32_t sb2 = sa + SB_OFF;
        const __nv_bfloat16* ga = At + ch * 32;
        const __nv_bfloat16* gb = Bt + ch * 32;
        CP16(sa + d0, ga + (size_t)r0i * ldK + s0 * 8);
        CP16(sa + d1, ga + (size_t)r1i * ldK + s1 * 8);
        CP16(sb2 + d0, gb + (size_t)r0i * ldK + s0 * 8);
        CP16(sb2 + d1, gb + (size_t)r1i * ldK + s1 * 8);
    };

    issue(0);
    CP_COMMIT();

    for (int ch = 0; ch < nchunks; ++ch) {
        if (ch + 1 < nchunks) {
            issue(ch + 1);
            CP_COMMIT();
            CP_WAIT1();
        } else {
            CP_WAIT0();
        }
        __syncthreads();

        const uint32_t sa = smb + (uint32_t)(ch & 1) * STG_BYTES;
        const uint32_t sb2 = sa + SB_OFF;
#pragma unroll
        for (int ks = 0; ks < 2; ++ks) {
            uint32_t afr[4][4], bfr[4][2];
#pragma unroll
            for (int mi = 0; mi < 4; ++mi)
                ldsm_x4(afr[mi], sa + aOff + mi * 1280 + ks * 32);
#pragma unroll
            for (int ni = 0; ni < 4; ++ni)
                ldsm_x2(bfr[ni], sb2 + bOff + ni * 640 + ks * 32);
#pragma unroll
            for (int mi = 0; mi < 4; ++mi)
#pragma unroll
                for (int ni = 0; ni < 4; ++ni)
                    mma16816(acc[mi][ni], afr[mi], bfr[ni]);
        }
        __syncthreads();
    }

    // epilogue: lane holds rows r, r+8 and cols c, c+1 per (mi, ni)
    const int rl = lid >> 2;
    const int cl = 2 * (lid & 3);

    if constexpr (MODE == 0 || MODE == 2) {
        float* Ob = OF + sOb * b;
#pragma unroll
        for (int mi = 0; mi < 4; ++mi) {
            const int rg = row0 + m_base + mi * 16 + rl;
#pragma unroll
            for (int ni = 0; ni < 4; ++ni) {
                const int cg = col0 + n_base + ni * 8 + cl;
                float bx = 0.f, by = 0.f;
                if constexpr (MODE == 0) { bx = p0[cg]; by = p0[cg + 1]; }
                *(float2*)(Ob + (size_t)rg * ldO + cg) =
                    make_float2(acc[mi][ni][0] + bx, acc[mi][ni][1] + by);
                *(float2*)(Ob + (size_t)(rg + 8) * ldO + cg) =
                    make_float2(acc[mi][ni][2] + bx, acc[mi][ni][3] + by);
            }
        }
    } else if constexpr (MODE == 1 || MODE == 3) {
        __nv_bfloat16* Ob = O3 + sOb * b;
        const int Kb = ldO / 3;
#pragma unroll
        for (int mi = 0; mi < 4; ++mi) {
#pragma unroll
            for (int ni = 0; ni < 4; ++ni) {
                const int cg = col0 + n_base + ni * 8 + cl;
#pragma unroll
                for (int half = 0; half < 2; ++half) {
                    float v0 = acc[mi][ni][2 * half + 0];
                    float v1 = acc[mi][ni][2 * half + 1];
                    if constexpr (MODE == 1) { v0 += p0[cg]; v1 += p0[cg + 1]; }
                    __nv_bfloat16 h0 = __float2bfloat16_rn(v0);
                    __nv_bfloat16 h1 = __float2bfloat16_rn(v1);
                    __nv_bfloat16 l0 = __float2bfloat16_rn(v0 - __bfloat162float(h0));
                    __nv_bfloat16 l1 = __float2bfloat16_rn(v1 - __bfloat162float(h1));
                    uint32_t hv = pack_bf2(h0, h1), lv = pack_bf2(l0, l1);
                    const int rg = row0 + m_base + mi * 16 + rl + half * 8;
                    __nv_bfloat16* pr = Ob + (size_t)rg * ldO + cg;
                    *(uint32_t*)(pr) = hv;
                    if constexpr (MODE == 1) {
                        *(uint32_t*)(pr + Kb) = lv;
                        *(uint32_t*)(pr + 2 * Kb) = hv;
                    } else {
                        *(uint32_t*)(pr + Kb) = hv;
                        *(uint32_t*)(pr + 2 * Kb) = lv;
                    }
                }
            }
        }
    } else { // MODE 4: rows are channels
        float* Ob = OF + sOb * b;
        const float* Xb = p5 + sOb * b;
#pragma unroll
        for (int mi = 0; mi < 4; ++mi) {
#pragma unroll
            for (int half = 0; half < 2; ++half) {
                const int c = row0 + m_base + mi * 16 + rl + half * 8;
                const float inv = p1[c] * rsqrtf(p4[c] + BN_EPS);
                const float sh = (p0[c] - p3[c]) * inv + p2[c];
#pragma unroll
                for (int ni = 0; ni < 4; ++ni) {
                    const int cg = col0 + n_base + ni * 8 + cl;
                    float2 xv = *(const float2*)(Xb + (size_t)c * ldO + cg);
                    *(float2*)(Ob + (size_t)c * ldO + cg) = make_float2(
                        acc[mi][ni][2 * half + 0] * inv + sh + xv.x,
                        acc[mi][ni][2 * half + 1] * inv + sh + xv.y);
                }
            }
        }
    }
}

// ---------------- x transpose-convert: x[b][c][n] -> x3[b][n][hi|lo|hi] -------
__global__ __launch_bounds__(256) void conv_x_kernel(const float* __restrict__ x)
{
    __shared__ float t[32][33];
    const int b = blockIdx.z;
    const int c0 = blockIdx.y * 32, n0 = blockIdx.x * 32;
    const int tx = threadIdx.x, ty = threadIdx.y;
    const float* X = x + (size_t)b * CC * NPIX;
#pragma unroll
    for (int i = 0; i < 4; ++i)
        t[ty + 8 * i][tx] = X[(size_t)(c0 + ty + 8 * i) * NPIX + n0 + tx];
    __syncthreads();
    __nv_bfloat16* O = d_x3 + (size_t)b * NPIX * (3 * CC);
#pragma unroll
    for (int i = 0; i < 4; ++i) {
        int n = n0 + ty + 8 * i;
        float v = t[tx][ty + 8 * i];
        __nv_bfloat16 h = __float2bfloat16_rn(v);
        __nv_bfloat16 l = __float2bfloat16_rn(v - __bfloat162float(h));
        __nv_bfloat16* row = O + (size_t)n * (3 * CC) + c0 + tx;
        row[0] = h; row[CC] = l; row[2 * CC] = h;
    }
}

// ---------------- weight convert ----------------------------------------------
__global__ void conv_w_kernel(const float* __restrict__ w, __nv_bfloat16* out,
                              int K, int total, int bpat)
{
    int idx = blockIdx.x * 256 + threadIdx.x;
    if (idx >= total) return;
    int r = idx / K, k = idx - r * K;
    float v = w[idx];
    __nv_bfloat16 h = __float2bfloat16_rn(v);
    __nv_bfloat16 l = __float2bfloat16_rn(v - __bfloat162float(h));
    __nv_bfloat16* row = out + (size_t)r * 3 * K;
    row[k] = h;
    row[K + k] = bpat ? h : l;
    row[2 * K + k] = bpat ? l : h;
}

// ---------------- pool: phiF/gF [b][n][ci] -> phiP3 [m][3ci], gP3 [ci][3m] ----
__global__ __launch_bounds__(128) void pool_kernel()
{
    const int m = blockIdx.x & (NPOOL - 1);
    const int b = blockIdx.x >> 10;
    const int ci = threadIdx.x;
    const int ph = m >> 5, pw = m & 31;
    const int n00 = (2 * ph) * WD + 2 * pw;
    const size_t base = ((size_t)b * NPIX + n00) * CI + ci;

    float p = fmaxf(fmaxf(d_phiF[base], d_phiF[base + CI]),
                    fmaxf(d_phiF[base + (size_t)WD * CI], d_phiF[base + (size_t)(WD + 1) * CI]));
    __nv_bfloat16 h = __float2bfloat16_rn(p);
    __nv_bfloat16 l = __float2bfloat16_rn(p - __bfloat162float(h));
    __nv_bfloat16* prow = d_phiP3 + ((size_t)b * NPOOL + m) * (3 * CI);
    prow[ci] = h; prow[CI + ci] = h; prow[2 * CI + ci] = l;   // B pattern hi|hi|lo

    float g = fmaxf(fmaxf(d_gF[base], d_gF[base + CI]),
                    fmaxf(d_gF[base + (size_t)WD * CI], d_gF[base + (size_t)(WD + 1) * CI]));
    __nv_bfloat16 gh = __float2bfloat16_rn(g);
    __nv_bfloat16 gl = __float2bfloat16_rn(g - __bfloat162float(gh));
    __nv_bfloat16* gc = d_gP3 + ((size_t)b * CI + ci) * (3 * NPOOL);
    gc[m] = gh; gc[NPOOL + m] = gh; gc[2 * NPOOL + m] = gl;   // B pattern hi|hi|lo
}

// ---------------- softmax over m, writes P3 trios (hi|lo|hi) -------------------
__global__ __launch_bounds__(256) void softmax_kernel()
{
    __shared__ float rmax[8], rsum[8], bval[2];
    const size_t row = blockIdx.x;
    const float4* p = (const float4*)(d_f + row * (size_t)NPOOL);
    const int tid = threadIdx.x;
    const int lane = tid & 31, wid = tid >> 5;

    float4 v = p[tid];
    float mx = fmaxf(fmaxf(v.x, v.y), fmaxf(v.z, v.w));
#pragma unroll
    for (int o = 16; o; o >>= 1) mx = fmaxf(mx, __shfl_xor_sync(0xffffffffu, mx, o));
    if (lane == 0) rmax[wid] = mx;
    __syncthreads();
    if (tid == 0) {
        float m = rmax[0];
#pragma unroll
        for (int i = 1; i < 8; ++i) m = fmaxf(m, rmax[i]);
        bval[0] = m;
    }
    __syncthreads();
    const float M = bval[0];
    v.x = expf(v.x - M); v.y = expf(v.y - M);
    v.z = expf(v.z - M); v.w = expf(v.w - M);
    float s = v.x + v.y + v.z + v.w;
#pragma unroll
    for (int o = 16; o; o >>= 1) s += __shfl_xor_sync(0xffffffffu, s, o);
    if (lane == 0) rsum[wid] = s;
    __syncthreads();
    if (tid == 0) {
        float t = 0.f;
#pragma unroll
        for (int i = 0; i < 8; ++i) t += rsum[i];
        bval[1] = 1.f / t;
    }
    __syncthreads();
    const float r = bval[1];
    v.x *= r; v.y *= r; v.z *= r; v.w *= r;

    __nv_bfloat16 h0 = __float2bfloat16_rn(v.x), h1 = __float2bfloat16_rn(v.y);
    __nv_bfloat16 h2 = __float2bfloat16_rn(v.z), h3 = __float2bfloat16_rn(v.w);
    __nv_bfloat16 l0 = __float2bfloat16_rn(v.x - __bfloat162float(h0));
    __nv_bfloat16 l1 = __float2bfloat16_rn(v.y - __bfloat162float(h1));
    __nv_bfloat16 l2 = __float2bfloat16_rn(v.z - __bfloat162float(h2));
    __nv_bfloat16 l3 = __float2bfloat16_rn(v.w - __bfloat162float(h3));
    __nv_bfloat16* row3 = d_P3 + row * (size_t)(3 * NPOOL);
    const int m0 = tid * 4;
    *(uint2*)(row3 + m0)             = make_uint2(pack_bf2(h0, h1), pack_bf2(h2, h3));
    *(uint2*)(row3 + NPOOL + m0)     = make_uint2(pack_bf2(l0, l1), pack_bf2(l2, l3));
    *(uint2*)(row3 + 2 * NPOOL + m0) = make_uint2(pack_bf2(h0, h1), pack_bf2(h2, h3));
}

// ---------------- launch --------------------------------------------------------
template <typename T>
static T* sym_addr(const void* sym)
{
    void* p = nullptr;
    cudaGetSymbolAddress(&p, sym);
    return (T*)p;
}

extern "C" void kernel_launch(void* const* d_in, const int* in_sizes, int n_in,
                              void* d_out, int out_size)
{
    const float* x    = (const float*)d_in[0];
    const float* g_w  = (const float*)d_in[1];
    const float* g_b  = (const float*)d_in[2];
    const float* th_w = (const float*)d_in[3];
    const float* th_b = (const float*)d_in[4];
    const float* ph_w = (const float*)d_in[5];
    const float* ph_b = (const float*)d_in[6];
    const float* W_w  = (const float*)d_in[7];
    const float* W_b  = (const float*)d_in[8];
    const float* gam  = (const float*)d_in[9];
    const float* bet  = (const float*)d_in[10];
    const float* mea  = (const float*)d_in[11];
    const float* var  = (const float*)d_in[12];
    float* out = (float*)d_out;

    __nv_bfloat16* x3   = sym_addr<__nv_bfloat16>(d_x3);
    __nv_bfloat16* w3t  = sym_addr<__nv_bfloat16>(d_w3t);
    __nv_bfloat16* w3p  = sym_addr<__nv_bfloat16>(d_w3p);
    __nv_bfloat16* w3g  = sym_addr<__nv_bfloat16>(d_w3g);
    __nv_bfloat16* Ww3  = sym_addr<__nv_bfloat16>(d_Ww3);
    __nv_bfloat16* th3  = sym_addr<__nv_bfloat16>(d_th3);
    float*         phiF = sym_addr<float>(d_phiF);
    float*         gF   = sym_addr<float>(d_gF);
    __nv_bfloat16* phiP3= sym_addr<__nv_bfloat16>(d_phiP3);
    __nv_bfloat16* gP3  = sym_addr<__nv_bfloat16>(d_gP3);
    float*         fbuf = sym_addr<float>(d_f);
    __nv_bfloat16* P3   = sym_addr<__nv_bfloat16>(d_P3);
    __nv_bfloat16* y3   = sym_addr<__nv_bfloat16>(d_y3);

    // converts
    conv_x_kernel<<<dim3(NPIX / 32, CC / 32, BB), dim3(32, 8)>>>(x);
    conv_w_kernel<<<(CI * CC + 255) / 256, 256>>>(th_w, w3t, CC, CI * CC, 1);
    conv_w_kernel<<<(CI * CC + 255) / 256, 256>>>(ph_w, w3p, CC, CI * CC, 1);
    conv_w_kernel<<<(CI * CC + 255) / 256, 256>>>(g_w,  w3g, CC, CI * CC, 1);
    conv_w_kernel<<<(CC * CI + 255) / 256, 256>>>(W_w,  Ww3, CI, CC * CI, 0);

    // projections: A=x3 [n][768], B=w3 [ci][768] -> D[n][ci]
    mma_gemm<1><<<dim3(1, 32, BB), 256>>>(
        x3, w3t, (size_t)NPIX * (3 * CC), 0, 3 * CC, 24,
        nullptr, th3, (size_t)NPIX * (3 * CI), 3 * CI, th_b, 0, 0, 0, 0, 0);
    mma_gemm<0><<<dim3(1, 32, BB), 256>>>(
        x3, w3p, (size_t)NPIX * (3 * CC), 0, 3 * CC, 24,
        phiF, nullptr, (size_t)NPIX * CI, CI, ph_b, 0, 0, 0, 0, 0);
    mma_gemm<0><<<dim3(1, 32, BB), 256>>>(
        x3, w3g, (size_t)NPIX * (3 * CC), 0, 3 * CC, 24,
        gF, nullptr, (size_t)NPIX * CI, CI, g_b, 0, 0, 0, 0, 0);

    pool_kernel<<<BB * NPOOL, 128>>>();

    // f: A=th3 [n][384], B=phiP3 [m][384] -> f[n][m]
    mma_gemm<2><<<dim3(NPOOL / 128, 32, BB), 256>>>(
        th3, phiP3, (size_t)NPIX * (3 * CI), (size_t)NPOOL * (3 * CI), 3 * CI, 12,
        fbuf, nullptr, (size_t)NPIX * NPOOL, NPOOL, nullptr, 0, 0, 0, 0, 0);

    softmax_kernel<<<BB * NPIX, 256>>>();

    // y: A=P3 [n][3072], B=gP3 [ci][3072] -> y3[n][3ci]
    mma_gemm<3><<<dim3(1, 32, BB), 256>>>(
        P3, gP3, (size_t)NPIX * (3 * NPOOL), (size_t)CI * (3 * NPOOL), 3 * NPOOL, 96,
        nullptr, y3, (size_t)NPIX * (3 * CI), 3 * CI, nullptr, 0, 0, 0, 0, 0);

    // out: A=Ww3 [c][384], B=y3 [n][384] -> out[b][c][n] with BN + residual
    mma_gemm<4><<<dim3(NPIX / 128, CC / 128, BB), 256>>>(
        Ww3, y3, 0, (size_t)NPIX * (3 * CI), 3 * CI, 12,
        out, nullptr, (size_t)CC * NPIX, NPIX, W_b, gam, bet, mea, var, x);
}

// round 5
// speedup vs baseline: 1.9350x; 1.1367x over previous
#include <cuda_runtime.h>
#include <cuda_bf16.h>
#include <math.h>
#include <stdint.h>

#define BB 8
#define CC 256
#define CI 128
#define NPIX 4096
#define NPOOL 1024
#define WD 64
#define BN_EPS 1e-5f

// ---------------- scratch (__device__ globals, no allocations) ----------------
__device__ __align__(16) __nv_bfloat16 d_x3  [(size_t)BB * NPIX * (3 * CC)];  // [b][n][hi|lo|hi]
__device__ __align__(16) __nv_bfloat16 d_w3all[(size_t)3 * CI * 3 * CC];      // theta|phi|g: [ci][hi|hi|lo]
__device__ __align__(16) __nv_bfloat16 d_Ww3 [(size_t)CC * 3 * CI];           // [c][hi|lo|hi]
__device__ __align__(16) __nv_bfloat16 d_th3 [(size_t)BB * NPIX * (3 * CI)];  // [b][n][hi|lo|hi]
__device__ __align__(16) float         d_phiF[(size_t)BB * NPIX * CI];        // [b][n][ci]
__device__ __align__(16) float         d_gF  [(size_t)BB * NPIX * CI];
__device__ __align__(16) __nv_bfloat16 d_phiP3[(size_t)BB * NPOOL * (3 * CI)];// [b][m][hi|hi|lo]
__device__ __align__(16) __nv_bfloat16 d_gPh [(size_t)BB * CI * NPOOL];       // [b][ci][m] hi
__device__ __align__(16) __nv_bfloat16 d_gPl [(size_t)BB * CI * NPOOL];       // [b][ci][m] lo
__device__ __align__(16) __nv_bfloat16 d_y3  [(size_t)BB * NPIX * (3 * CI)];  // [b][n][hi|hi|lo]

// ---------------- helpers -------------------------------------------------------
__device__ __forceinline__ uint32_t smem_u32(const void* p) {
    uint32_t a;
    asm("{ .reg .u64 t; cvta.to.shared.u64 t, %1; cvt.u32.u64 %0, t; }" : "=r"(a) : "l"(p));
    return a;
}
__device__ __forceinline__ uint32_t pack_bf2(__nv_bfloat16 a, __nv_bfloat16 b) {
    __nv_bfloat162 h(a, b);
    return *(uint32_t*)&h;
}
#define CP16(dst, src) asm volatile("cp.async.ca.shared.global [%0], [%1], 16;" :: "r"(dst), "l"(src))
#define CP_COMMIT()    asm volatile("cp.async.commit_group;" ::: "memory")
#define CP_WAIT1()     asm volatile("cp.async.wait_group 1;" ::: "memory")
#define CP_WAIT0()     asm volatile("cp.async.wait_group 0;" ::: "memory")

__device__ __forceinline__ void ldsm_x4(uint32_t* r, uint32_t addr) {
    asm volatile("ldmatrix.sync.aligned.m8n8.x4.shared.b16 {%0,%1,%2,%3}, [%4];"
                 : "=r"(r[0]), "=r"(r[1]), "=r"(r[2]), "=r"(r[3]) : "r"(addr));
}
__device__ __forceinline__ void ldsm_x2(uint32_t* r, uint32_t addr) {
    asm volatile("ldmatrix.sync.aligned.m8n8.x2.shared.b16 {%0,%1}, [%2];"
                 : "=r"(r[0]), "=r"(r[1]) : "r"(addr));
}
__device__ __forceinline__ void mma16816(float* c, const uint32_t* a, const uint32_t* b) {
    asm volatile("mma.sync.aligned.m16n8k16.row.col.f32.bf16.bf16.f32 "
                 "{%0,%1,%2,%3}, {%4,%5,%6,%7}, {%8,%9}, {%0,%1,%2,%3};"
                 : "+f"(c[0]), "+f"(c[1]), "+f"(c[2]), "+f"(c[3])
                 : "r"(a[0]), "r"(a[1]), "r"(a[2]), "r"(a[3]), "r"(b[0]), "r"(b[1]));
}

// ============ generic warp-mma GEMM (proj + out), K-chunks of 32 ================
#define STG_BYTES 20480
#define SB_OFF    10240

// MODE 4: fp32 out + BN(row) + residual (p0=Wb p1=gamma p2=beta p3=mean p4=var p5=x)
// MODE 5: merged projections. blockIdx.z = which*8 + b. which0: trio->d_th3 (+p0);
//         which1: fp32->d_phiF (+p1); which2: fp32->d_gF (+p2)
template <int MODE>
__global__ __launch_bounds__(256) void mma_gemm(
    const __nv_bfloat16* __restrict__ A, const __nv_bfloat16* __restrict__ B,
    size_t sAb, size_t sBb, int ldK, int nchunks,
    float* OF, size_t sOb, int ldO,
    const float* __restrict__ p0, const float* __restrict__ p1,
    const float* __restrict__ p2, const float* __restrict__ p3,
    const float* __restrict__ p4, const float* __restrict__ p5)
{
    __shared__ __align__(16) char sm[2 * STG_BYTES];
    const uint32_t smb = smem_u32(sm);
    const int tid = threadIdx.x;
    const int wid = tid >> 5, lid = tid & 31;
    const int b = (MODE == 5) ? (blockIdx.z & 7) : blockIdx.z;
    const int which = (MODE == 5) ? (blockIdx.z >> 3) : 0;
    const int row0 = blockIdx.y * 128, col0 = blockIdx.x * 128;
    const int m_base = (wid & 1) * 64;
    const int n_base = (wid >> 1) * 32;

    const __nv_bfloat16* At = A + sAb * b + (size_t)row0 * ldK;
    const __nv_bfloat16* Bt = B + sBb * (size_t)((MODE == 5) ? which : b) + (size_t)col0 * ldK;

    const int r0i = tid >> 2, s0 = (tid & 3);
    const int r1i = (tid + 256) >> 2;
    const uint32_t d0 = (uint32_t)(r0i * 80 + s0 * 16);
    const uint32_t d1 = (uint32_t)(r1i * 80 + s0 * 16);
    const uint32_t aOff = (uint32_t)((m_base + (lid & 15)) * 80 + (lid >> 4) * 16);
    const uint32_t bOff = (uint32_t)((n_base + (lid & 7)) * 80 + ((lid >> 3) & 1) * 16);

    float acc[4][4][4] = {};

    auto issue = [&](int ch) {
        const uint32_t sa = smb + (uint32_t)(ch & 1) * STG_BYTES;
        const uint32_t sb2 = sa + SB_OFF;
        const __nv_bfloat16* ga = At + ch * 32;
        const __nv_bfloat16* gb = Bt + ch * 32;
        CP16(sa + d0, ga + (size_t)r0i * ldK + s0 * 8);
        CP16(sa + d1, ga + (size_t)r1i * ldK + s0 * 8);
        CP16(sb2 + d0, gb + (size_t)r0i * ldK + s0 * 8);
        CP16(sb2 + d1, gb + (size_t)r1i * ldK + s0 * 8);
    };

    issue(0);
    CP_COMMIT();
    for (int ch = 0; ch < nchunks; ++ch) {
        if (ch + 1 < nchunks) { issue(ch + 1); CP_COMMIT(); CP_WAIT1(); }
        else CP_WAIT0();
        __syncthreads();
        const uint32_t sa = smb + (uint32_t)(ch & 1) * STG_BYTES;
        const uint32_t sb2 = sa + SB_OFF;
#pragma unroll
        for (int ks = 0; ks < 2; ++ks) {
            uint32_t afr[4][4], bfr[4][2];
#pragma unroll
            for (int mi = 0; mi < 4; ++mi) ldsm_x4(afr[mi], sa + aOff + mi * 1280 + ks * 32);
#pragma unroll
            for (int ni = 0; ni < 4; ++ni) ldsm_x2(bfr[ni], sb2 + bOff + ni * 640 + ks * 32);
#pragma unroll
            for (int mi = 0; mi < 4; ++mi)
#pragma unroll
                for (int ni = 0; ni < 4; ++ni) mma16816(acc[mi][ni], afr[mi], bfr[ni]);
        }
        __syncthreads();
    }

    const int rl = lid >> 2;
    const int cl = 2 * (lid & 3);

    if constexpr (MODE == 4) {
        float* Ob = OF + sOb * b;
        const float* Xb = p5 + sOb * b;
#pragma unroll
        for (int mi = 0; mi < 4; ++mi)
#pragma unroll
            for (int half = 0; half < 2; ++half) {
                const int c = row0 + m_base + mi * 16 + rl + half * 8;
                const float inv = p1[c] * rsqrtf(p4[c] + BN_EPS);
                const float sh = (p0[c] - p3[c]) * inv + p2[c];
#pragma unroll
                for (int ni = 0; ni < 4; ++ni) {
                    const int cg = col0 + n_base + ni * 8 + cl;
                    float2 xv = *(const float2*)(Xb + (size_t)c * ldO + cg);
                    *(float2*)(Ob + (size_t)c * ldO + cg) = make_float2(
                        acc[mi][ni][2 * half + 0] * inv + sh + xv.x,
                        acc[mi][ni][2 * half + 1] * inv + sh + xv.y);
                }
            }
    } else { // MODE 5
        if (which == 0) {
            __nv_bfloat16* Ob = d_th3 + (size_t)b * NPIX * (3 * CI);
#pragma unroll
            for (int mi = 0; mi < 4; ++mi)
#pragma unroll
                for (int ni = 0; ni < 4; ++ni) {
                    const int cg = col0 + n_base + ni * 8 + cl;
#pragma unroll
                    for (int half = 0; half < 2; ++half) {
                        float v0 = acc[mi][ni][2 * half + 0] + p0[cg];
                        float v1 = acc[mi][ni][2 * half + 1] + p0[cg + 1];
                        __nv_bfloat16 h0 = __float2bfloat16_rn(v0);
                        __nv_bfloat16 h1 = __float2bfloat16_rn(v1);
                        __nv_bfloat16 l0 = __float2bfloat16_rn(v0 - __bfloat162float(h0));
                        __nv_bfloat16 l1 = __float2bfloat16_rn(v1 - __bfloat162float(h1));
                        const int rg = row0 + m_base + mi * 16 + rl + half * 8;
                        __nv_bfloat16* pr = Ob + (size_t)rg * (3 * CI) + cg;
                        *(uint32_t*)(pr)          = pack_bf2(h0, h1);
                        *(uint32_t*)(pr + CI)     = pack_bf2(l0, l1);
                        *(uint32_t*)(pr + 2 * CI) = pack_bf2(h0, h1);
                    }
                }
        } else {
            float* Ob = (which == 1 ? d_phiF : d_gF) + (size_t)b * NPIX * CI;
            const float* bias = (which == 1) ? p1 : p2;
#pragma unroll
            for (int mi = 0; mi < 4; ++mi) {
                const int rg = row0 + m_base + mi * 16 + rl;
#pragma unroll
                for (int ni = 0; ni < 4; ++ni) {
                    const int cg = col0 + n_base + ni * 8 + cl;
                    float bx = bias[cg], by = bias[cg + 1];
                    *(float2*)(Ob + (size_t)rg * CI + cg) =
                        make_float2(acc[mi][ni][0] + bx, acc[mi][ni][1] + by);
                    *(float2*)(Ob + (size_t)(rg + 8) * CI + cg) =
                        make_float2(acc[mi][ni][2] + bx, acc[mi][ni][3] + by);
                }
            }
        }
    }
}

// ============ flash kernel: S = th3*phiP3^T, online softmax, Y = P*g ============
#define FL_PITCH1 144
#define FL_PITCHP 272
#define FS_A    0
#define FS_B    (FS_A + 2 * 18432)
#define FS_PH   (FS_B + 2 * 18432)          // 73728
#define FS_PL   (FS_PH + 34816)
#define FS_GH   (FS_PL + 34816)
#define FS_GL   (FS_GH + 34816)
#define FS_RED  (FS_GL + 34816)             // 128*4 floats
#define FS_RMAX (FS_RED + 2048)
#define FS_RSUM (FS_RMAX + 512)
#define FS_RSC  (FS_RSUM + 512)
#define FS_RBC  (FS_RSC + 512)
#define FL_SMEM (FS_RBC + 512)              // 217088 bytes

__global__ __launch_bounds__(256, 1) void flash_kernel()
{
    extern __shared__ __align__(16) char sm[];
    const uint32_t smb = smem_u32(sm);
    float* red  = (float*)(sm + FS_RED);
    float* rmax = (float*)(sm + FS_RMAX);
    float* rsum = (float*)(sm + FS_RSUM);
    float* rsc  = (float*)(sm + FS_RSC);
    float* rbc  = (float*)(sm + FS_RBC);

    const int tid = threadIdx.x, wid = tid >> 5, lid = tid & 31;
    const int b = blockIdx.y;
    const int n0 = blockIdx.x * 128;
    const int mrow = (wid & 1) * 64;
    const int ncol = (wid >> 1) * 32;
    const int rl = lid >> 2, cl = 2 * (lid & 3);

    const __nv_bfloat16* At = d_th3 + (size_t)b * NPIX * 384 + (size_t)n0 * 384;
    const __nv_bfloat16* Pt = d_phiP3 + (size_t)b * NPOOL * 384;
    const __nv_bfloat16* Gh = d_gPh + (size_t)b * CI * NPOOL;
    const __nv_bfloat16* Gl = d_gPl + (size_t)b * CI * NPOOL;

    if (tid < 128) { rmax[tid] = -1e30f; rsum[tid] = 0.f; }
    __syncthreads();

    const uint32_t a1 = (uint32_t)((mrow + (lid & 15)) * FL_PITCH1 + (lid >> 4) * 16);
    const uint32_t b1 = (uint32_t)((ncol + (lid & 7)) * FL_PITCH1 + ((lid >> 3) & 1) * 16);
    const uint32_t a2 = (uint32_t)((mrow + (lid & 15)) * FL_PITCHP + (lid >> 4) * 16);
    const uint32_t b2 = (uint32_t)((ncol + (lid & 7)) * FL_PITCHP + ((lid >> 3) & 1) * 16);

    float accY[4][4][4] = {};

    for (int mt = 0; mt < 8; ++mt) {
        const int m0 = mt * 128;

        // g tile loads (group issued first, completes first)
        {
            const uint32_t gh = smb + FS_GH, gl = smb + FS_GL;
#pragma unroll
            for (int t = 0; t < 8; ++t) {
                int j = tid + 256 * t;
                int row = j >> 4, seg = j & 15;
                uint32_t dst = (uint32_t)(row * FL_PITCHP + seg * 16);
                CP16(gh + dst, Gh + (size_t)row * NPOOL + m0 + seg * 8);
                CP16(gl + dst, Gl + (size_t)row * NPOOL + m0 + seg * 8);
            }
            CP_COMMIT();
        }

        auto issue1 = [&](int ch) {
            const uint32_t sa = smb + FS_A + (uint32_t)(ch & 1) * 18432;
            const uint32_t sbb = smb + FS_B + (uint32_t)(ch & 1) * 18432;
            const int k0 = ch * 64;
#pragma unroll
            for (int t = 0; t < 4; ++t) {
                int j = tid + 256 * t;
                int row = j >> 3, seg = j & 7;
                uint32_t dst = (uint32_t)(row * FL_PITCH1 + seg * 16);
                CP16(sa + dst, At + (size_t)row * 384 + k0 + seg * 8);
                CP16(sbb + dst, Pt + (size_t)(m0 + row) * 384 + k0 + seg * 8);
            }
            CP_COMMIT();
        };

        float accS[4][4][4] = {};
        issue1(0);
        for (int ch = 0; ch < 6; ++ch) {
            if (ch + 1 < 6) { issue1(ch + 1); CP_WAIT1(); }
            else CP_WAIT0();
            __syncthreads();
            const uint32_t sa = smb + FS_A + (uint32_t)(ch & 1) * 18432;
            const uint32_t sbb = smb + FS_B + (uint32_t)(ch & 1) * 18432;
#pragma unroll
            for (int ks = 0; ks < 4; ++ks) {
                uint32_t afr[4][4], bfr[4][2];
#pragma unroll
                for (int mi = 0; mi < 4; ++mi) ldsm_x4(afr[mi], sa + a1 + mi * 16 * FL_PITCH1 + ks * 32);
#pragma unroll
                for (int ni = 0; ni < 4; ++ni) ldsm_x2(bfr[ni], sbb + b1 + ni * 8 * FL_PITCH1 + ks * 32);
#pragma unroll
                for (int mi = 0; mi < 4; ++mi)
#pragma unroll
                    for (int ni = 0; ni < 4; ++ni) mma16816(accS[mi][ni], afr[mi], bfr[ni]);
            }
            __syncthreads();
        }

        // ---- online softmax ----
#pragma unroll
        for (int mi = 0; mi < 4; ++mi)
#pragma unroll
            for (int half = 0; half < 2; ++half) {
                float v = -1e30f;
#pragma unroll
                for (int ni = 0; ni < 4; ++ni)
                    v = fmaxf(v, fmaxf(accS[mi][ni][2 * half], accS[mi][ni][2 * half + 1]));
                v = fmaxf(v, __shfl_xor_sync(0xffffffffu, v, 1));
                v = fmaxf(v, __shfl_xor_sync(0xffffffffu, v, 2));
                if ((lid & 3) == 0)
                    red[(mrow + mi * 16 + rl + half * 8) * 4 + (wid >> 1)] = v;
            }
        __syncthreads();
        if (tid < 128) {
            float mOld = rmax[tid];
            float mNew = fmaxf(fmaxf(red[tid * 4], red[tid * 4 + 1]),
                               fmaxf(red[tid * 4 + 2], red[tid * 4 + 3]));
            mNew = fmaxf(mOld, mNew);
            rbc[tid] = mNew; rsc[tid] = __expf(mOld - mNew); rmax[tid] = mNew;
        }
        __syncthreads();
#pragma unroll
        for (int mi = 0; mi < 4; ++mi)
#pragma unroll
            for (int half = 0; half < 2; ++half) {
                const int r = mrow + mi * 16 + rl + half * 8;
                const float mb = rbc[r];
                const float sc = rsc[r];
                float s = 0.f;
#pragma unroll
                for (int ni = 0; ni < 4; ++ni) {
                    accY[mi][ni][2 * half]     *= sc;
                    accY[mi][ni][2 * half + 1] *= sc;
                    float e0 = __expf(accS[mi][ni][2 * half]     - mb);
                    float e1 = __expf(accS[mi][ni][2 * half + 1] - mb);
                    s += e0 + e1;
                    __nv_bfloat16 h0 = __float2bfloat16_rn(e0);
                    __nv_bfloat16 h1 = __float2bfloat16_rn(e1);
                    __nv_bfloat16 l0 = __float2bfloat16_rn(e0 - __bfloat162float(h0));
                    __nv_bfloat16 l1 = __float2bfloat16_rn(e1 - __bfloat162float(h1));
                    const uint32_t off = (uint32_t)(r * FL_PITCHP + (ncol + ni * 8 + cl) * 2);
                    *(uint32_t*)(sm + FS_PH + off) = pack_bf2(h0, h1);
                    *(uint32_t*)(sm + FS_PL + off) = pack_bf2(l0, l1);
                }
                s += __shfl_xor_sync(0xffffffffu, s, 1);
                s += __shfl_xor_sync(0xffffffffu, s, 2);
                if ((lid & 3) == 0) red[r * 4 + (wid >> 1)] = s;
            }
        __syncthreads();
        if (tid < 128)
            rsum[tid] = rsum[tid] * rsc[tid] +
                        (red[tid * 4] + red[tid * 4 + 1] + red[tid * 4 + 2] + red[tid * 4 + 3]);

        // ---- phase 2: Y += P_hi*g_hi + P_lo*g_hi + P_hi*g_lo ----
        const uint32_t pbuf[3] = { smb + FS_PH, smb + FS_PL, smb + FS_PH };
        const uint32_t gbuf[3] = { smb + FS_GH, smb + FS_GH, smb + FS_GL };
#pragma unroll
        for (int pass = 0; pass < 3; ++pass) {
            const uint32_t ab = pbuf[pass] + a2;
            const uint32_t bb = gbuf[pass] + b2;
#pragma unroll
            for (int ks = 0; ks < 8; ++ks) {
                uint32_t afr[4][4], bfr[4][2];
#pragma unroll
                for (int mi = 0; mi < 4; ++mi) ldsm_x4(afr[mi], ab + mi * 16 * FL_PITCHP + ks * 32);
#pragma unroll
                for (int ni = 0; ni < 4; ++ni) ldsm_x2(bfr[ni], bb + ni * 8 * FL_PITCHP + ks * 32);
#pragma unroll
                for (int mi = 0; mi < 4; ++mi)
#pragma unroll
                    for (int ni = 0; ni < 4; ++ni) mma16816(accY[mi][ni], afr[mi], bfr[ni]);
            }
        }
        __syncthreads();   // protect P/g/red buffers before next tile
    }

    // ---- epilogue: normalize, write y3 trio (hi|hi|lo) ----
    __nv_bfloat16* Ob = d_y3 + (size_t)b * NPIX * 384 + (size_t)n0 * 384;
#pragma unroll
    for (int mi = 0; mi < 4; ++mi)
#pragma unroll
        for (int half = 0; half < 2; ++half) {
            const int r = mrow + mi * 16 + rl + half * 8;
            const float rinv = 1.f / rsum[r];
#pragma unroll
            for (int ni = 0; ni < 4; ++ni) {
                float v0 = accY[mi][ni][2 * half]     * rinv;
                float v1 = accY[mi][ni][2 * half + 1] * rinv;
                __nv_bfloat16 h0 = __float2bfloat16_rn(v0);
                __nv_bfloat16 h1 = __float2bfloat16_rn(v1);
                __nv_bfloat16 l0 = __float2bfloat16_rn(v0 - __bfloat162float(h0));
                __nv_bfloat16 l1 = __float2bfloat16_rn(v1 - __bfloat162float(h1));
                __nv_bfloat16* pr = Ob + (size_t)r * 384 + (ncol + ni * 8 + cl);
                *(uint32_t*)(pr)          = pack_bf2(h0, h1);
                *(uint32_t*)(pr + CI)     = pack_bf2(h0, h1);
                *(uint32_t*)(pr + 2 * CI) = pack_bf2(l0, l1);
            }
        }
}

// ---------------- x transpose-convert ------------------------------------------
__global__ __launch_bounds__(256) void conv_x_kernel(const float* __restrict__ x)
{
    __shared__ float t[32][33];
    const int b = blockIdx.z;
    const int c0 = blockIdx.y * 32, n0 = blockIdx.x * 32;
    const int tx = threadIdx.x, ty = threadIdx.y;
    const float* X = x + (size_t)b * CC * NPIX;
#pragma unroll
    for (int i = 0; i < 4; ++i)
        t[ty + 8 * i][tx] = X[(size_t)(c0 + ty + 8 * i) * NPIX + n0 + tx];
    __syncthreads();
    __nv_bfloat16* O = d_x3 + (size_t)b * NPIX * (3 * CC);
#pragma unroll
    for (int i = 0; i < 4; ++i) {
        int n = n0 + ty + 8 * i;
        float v = t[tx][ty + 8 * i];
        __nv_bfloat16 h = __float2bfloat16_rn(v);
        __nv_bfloat16 l = __float2bfloat16_rn(v - __bfloat162float(h));
        __nv_bfloat16* row = O + (size_t)n * (3 * CC) + c0 + tx;
        row[0] = h; row[CC] = l; row[2 * CC] = h;
    }
}

// ---------------- weight convert ------------------------------------------------
__global__ void conv_w_kernel(const float* __restrict__ w, __nv_bfloat16* out,
                              int K, int total, int bpat)
{
    int idx = blockIdx.x * 256 + threadIdx.x;
    if (idx >= total) return;
    int r = idx / K, k = idx - r * K;
    float v = w[idx];
    __nv_bfloat16 h = __float2bfloat16_rn(v);
    __nv_bfloat16 l = __float2bfloat16_rn(v - __bfloat162float(h));
    __nv_bfloat16* row = out + (size_t)r * 3 * K;
    row[k] = h;
    row[K + k] = bpat ? h : l;
    row[2 * K + k] = bpat ? l : h;
}

// ---------------- pool -----------------------------------------------------------
__global__ __launch_bounds__(128) void pool_kernel()
{
    const int m = blockIdx.x & (NPOOL - 1);
    const int b = blockIdx.x >> 10;
    const int ci = threadIdx.x;
    const int ph = m >> 5, pw = m & 31;
    const int n00 = (2 * ph) * WD + 2 * pw;
    const size_t base = ((size_t)b * NPIX + n00) * CI + ci;

    float p = fmaxf(fmaxf(d_phiF[base], d_phiF[base + CI]),
                    fmaxf(d_phiF[base + (size_t)WD * CI], d_phiF[base + (size_t)(WD + 1) * CI]));
    __nv_bfloat16 h = __float2bfloat16_rn(p);
    __nv_bfloat16 l = __float2bfloat16_rn(p - __bfloat162float(h));
    __nv_bfloat16* prow = d_phiP3 + ((size_t)b * NPOOL + m) * (3 * CI);
    prow[ci] = h; prow[CI + ci] = h; prow[2 * CI + ci] = l;

    float g = fmaxf(fmaxf(d_gF[base], d_gF[base + CI]),
                    fmaxf(d_gF[base + (size_t)WD * CI], d_gF[base + (size_t)(WD + 1) * CI]));
    __nv_bfloat16 gh = __float2bfloat16_rn(g);
    __nv_bfloat16 gl = __float2bfloat16_rn(g - __bfloat162float(gh));
    d_gPh[((size_t)b * CI + ci) * NPOOL + m] = gh;
    d_gPl[((size_t)b * CI + ci) * NPOOL + m] = gl;
}

// ---------------- launch ----------------------------------------------------------
template <typename T>
static T* sym_addr(const void* sym)
{
    void* p = nullptr;
    cudaGetSymbolAddress(&p, sym);
    return (T*)p;
}

extern "C" void kernel_launch(void* const* d_in, const int* in_sizes, int n_in,
                              void* d_out, int out_size)
{
    const float* x    = (const float*)d_in[0];
    const float* g_w  = (const float*)d_in[1];
    const float* g_b  = (const float*)d_in[2];
    const float* th_w = (const float*)d_in[3];
    const float* th_b = (const float*)d_in[4];
    const float* ph_w = (const float*)d_in[5];
    const float* ph_b = (const float*)d_in[6];
    const float* W_w  = (const float*)d_in[7];
    const float* W_b  = (const float*)d_in[8];
    const float* gam  = (const float*)d_in[9];
    const float* bet  = (const float*)d_in[10];
    const float* mea  = (const float*)d_in[11];
    const float* var  = (const float*)d_in[12];
    float* out = (float*)d_out;

    __nv_bfloat16* x3    = sym_addr<__nv_bfloat16>(d_x3);
    __nv_bfloat16* w3all = sym_addr<__nv_bfloat16>(d_w3all);
    __nv_bfloat16* Ww3   = sym_addr<__nv_bfloat16>(d_Ww3);
    __nv_bfloat16* y3    = sym_addr<__nv_bfloat16>(d_y3);

    cudaFuncSetAttribute(flash_kernel, cudaFuncAttributeMaxDynamicSharedMemorySize, FL_SMEM);

    conv_x_kernel<<<dim3(NPIX / 32, CC / 32, BB), dim3(32, 8)>>>(x);
    conv_w_kernel<<<(CI * CC + 255) / 256, 256>>>(th_w, w3all,                   CC, CI * CC, 1);
    conv_w_kernel<<<(CI * CC + 255) / 256, 256>>>(ph_w, w3all + (size_t)CI * 768, CC, CI * CC, 1);
    conv_w_kernel<<<(CI * CC + 255) / 256, 256>>>(g_w,  w3all + (size_t)2 * CI * 768, CC, CI * CC, 1);
    conv_w_kernel<<<(CC * CI + 255) / 256, 256>>>(W_w,  Ww3, CI, CC * CI, 0);

    // merged projections: z = which*8 + b
    mma_gemm<5><<<dim3(1, 32, 24), 256>>>(
        x3, w3all, (size_t)NPIX * 768, (size_t)CI * 768, 768, 24,
        nullptr, 0, 0, th_b, ph_b, g_b, nullptr, nullptr, nullptr);

    pool_kernel<<<BB * NPOOL, 128>>>();

    flash_kernel<<<dim3(NPIX / 128, BB), 256, FL_SMEM>>>();

    mma_gemm<4><<<dim3(NPIX / 128, CC / 128, BB), 256>>>(
        Ww3, y3, 0, (size_t)NPIX * 384, 384, 12,
        out, (size_t)CC * NPIX, NPIX, W_b, gam, bet, mea, var, x);
}

// round 6
// speedup vs baseline: 2.0572x; 1.0631x over previous
#include <cuda_runtime.h>
#include <cuda_bf16.h>
#include <math.h>
#include <stdint.h>

#define BB 8
#define CC 256
#define CI 128
#define NPIX 4096
#define NPOOL 1024
#define WD 64
#define BN_EPS 1e-5f

// ---------------- scratch (__device__ globals, no allocations) ----------------
__device__ __align__(16) __nv_bfloat16 d_x2  [(size_t)BB * NPIX * (2 * CC)];  // [b][n][hi|lo]
__device__ __align__(16) __nv_bfloat16 d_w2all[(size_t)3 * CI * 2 * CC];      // theta|phi|g: [ci][hi|lo]
__device__ __align__(16) __nv_bfloat16 d_Ww2 [(size_t)CC * 2 * CI];           // [c][hi|lo]
__device__ __align__(16) __nv_bfloat16 d_th2 [(size_t)BB * NPIX * (2 * CI)];  // [b][n][hi|lo]
__device__ __align__(16) float         d_phiF[(size_t)BB * NPIX * CI];        // [b][n][ci]
__device__ __align__(16) float         d_gF  [(size_t)BB * NPIX * CI];
__device__ __align__(16) __nv_bfloat16 d_phiP2[(size_t)BB * NPOOL * (2 * CI)];// [b][m][hi|lo]
__device__ __align__(16) __nv_bfloat16 d_gPh [(size_t)BB * CI * NPOOL];       // [b][ci][m] hi
__device__ __align__(16) __nv_bfloat16 d_gPl [(size_t)BB * CI * NPOOL];       // [b][ci][m] lo
__device__ __align__(16) __nv_bfloat16 d_y2  [(size_t)BB * NPIX * (2 * CI)];  // [b][n][hi|lo]

// ---------------- helpers -------------------------------------------------------
__device__ __forceinline__ uint32_t smem_u32(const void* p) {
    uint32_t a;
    asm("{ .reg .u64 t; cvta.to.shared.u64 t, %1; cvt.u32.u64 %0, t; }" : "=r"(a) : "l"(p));
    return a;
}
__device__ __forceinline__ uint32_t pack_bf2(__nv_bfloat16 a, __nv_bfloat16 b) {
    __nv_bfloat162 h(a, b);
    return *(uint32_t*)&h;
}
#define CP16(dst, src) asm volatile("cp.async.ca.shared.global [%0], [%1], 16;" :: "r"(dst), "l"(src))
#define CP_COMMIT()    asm volatile("cp.async.commit_group;" ::: "memory")
#define CP_WAIT1()     asm volatile("cp.async.wait_group 1;" ::: "memory")
#define CP_WAIT0()     asm volatile("cp.async.wait_group 0;" ::: "memory")

__device__ __forceinline__ void ldsm_x4(uint32_t* r, uint32_t addr) {
    asm volatile("ldmatrix.sync.aligned.m8n8.x4.shared.b16 {%0,%1,%2,%3}, [%4];"
                 : "=r"(r[0]), "=r"(r[1]), "=r"(r[2]), "=r"(r[3]) : "r"(addr));
}
__device__ __forceinline__ void ldsm_x2(uint32_t* r, uint32_t addr) {
    asm volatile("ldmatrix.sync.aligned.m8n8.x2.shared.b16 {%0,%1}, [%2];"
                 : "=r"(r[0]), "=r"(r[1]) : "r"(addr));
}
__device__ __forceinline__ void mma16816(float* c, const uint32_t* a, const uint32_t* b) {
    asm volatile("mma.sync.aligned.m16n8k16.row.col.f32.bf16.bf16.f32 "
                 "{%0,%1,%2,%3}, {%4,%5,%6,%7}, {%8,%9}, {%0,%1,%2,%3};"
                 : "+f"(c[0]), "+f"(c[1]), "+f"(c[2]), "+f"(c[3])
                 : "r"(a[0]), "r"(a[1]), "r"(a[2]), "r"(a[3]), "r"(b[0]), "r"(b[1]));
}

// ============ generic warp-mma GEMM with split-pass K slices =====================
// D = A_hi*B_hi + A_lo*B_hi + A_hi*B_lo over 3 passes; ch -> (pass, kk):
//   aK = (p==1?KB:0)+kk*32, bK = (p==2?KB:0)+kk*32.  nchunks = 3*KB/32.
#define STG_BYTES 20480
#define SB_OFF    10240

// MODE 4: fp32 out + BN(row) + residual (p0=Wb p1=gamma p2=beta p3=mean p4=var p5=x)
// MODE 5: merged projections; blockIdx.z = which*8 + b.
//         which0: duo->d_th2 (+p0); which1: fp32->d_phiF (+p1); which2: fp32->d_gF (+p2)
template <int MODE, int KB>
__global__ __launch_bounds__(256) void mma_gemm(
    const __nv_bfloat16* __restrict__ A, const __nv_bfloat16* __restrict__ B,
    size_t sAb, size_t sBb,
    float* OF, size_t sOb, int ldO,
    const float* __restrict__ p0, const float* __restrict__ p1,
    const float* __restrict__ p2, const float* __restrict__ p3,
    const float* __restrict__ p4, const float* __restrict__ p5)
{
    constexpr int ldK = 2 * KB;
    constexpr int k32pp = KB / 32;
    constexpr int nchunks = 3 * k32pp;

    __shared__ __align__(16) char sm[2 * STG_BYTES];
    const uint32_t smb = smem_u32(sm);
    const int tid = threadIdx.x;
    const int wid = tid >> 5, lid = tid & 31;
    const int b = (MODE == 5) ? (blockIdx.z & 7) : blockIdx.z;
    const int which = (MODE == 5) ? (blockIdx.z >> 3) : 0;
    const int row0 = blockIdx.y * 128, col0 = blockIdx.x * 128;
    const int m_base = (wid & 1) * 64;
    const int n_base = (wid >> 1) * 32;

    const __nv_bfloat16* At = A + sAb * b + (size_t)row0 * ldK;
    const __nv_bfloat16* Bt = B + sBb * (size_t)((MODE == 5) ? which : b) + (size_t)col0 * ldK;

    const int r0i = tid >> 2, s0 = (tid & 3);
    const int r1i = (tid + 256) >> 2;
    const uint32_t d0 = (uint32_t)(r0i * 80 + s0 * 16);
    const uint32_t d1 = (uint32_t)(r1i * 80 + s0 * 16);
    const uint32_t aOff = (uint32_t)((m_base + (lid & 15)) * 80 + (lid >> 4) * 16);
    const uint32_t bOff = (uint32_t)((n_base + (lid & 7)) * 80 + ((lid >> 3) & 1) * 16);

    float acc[4][4][4] = {};

    auto issue = [&](int ch) {
        const int p = ch / k32pp, kk = ch - p * k32pp;
        const int aK = (p == 1 ? KB : 0) + kk * 32;
        const int bK = (p == 2 ? KB : 0) + kk * 32;
        const uint32_t sa = smb + (uint32_t)(ch & 1) * STG_BYTES;
        const uint32_t sb2 = sa + SB_OFF;
        const __nv_bfloat16* ga = At + aK;
        const __nv_bfloat16* gb = Bt + bK;
        CP16(sa + d0, ga + (size_t)r0i * ldK + s0 * 8);
        CP16(sa + d1, ga + (size_t)r1i * ldK + s0 * 8);
        CP16(sb2 + d0, gb + (size_t)r0i * ldK + s0 * 8);
        CP16(sb2 + d1, gb + (size_t)r1i * ldK + s0 * 8);
    };

    issue(0);
    CP_COMMIT();
    for (int ch = 0; ch < nchunks; ++ch) {
        if (ch + 1 < nchunks) { issue(ch + 1); CP_COMMIT(); CP_WAIT1(); }
        else CP_WAIT0();
        __syncthreads();
        const uint32_t sa = smb + (uint32_t)(ch & 1) * STG_BYTES;
        const uint32_t sb2 = sa + SB_OFF;
#pragma unroll
        for (int ks = 0; ks < 2; ++ks) {
            uint32_t afr[4][4], bfr[4][2];
#pragma unroll
            for (int mi = 0; mi < 4; ++mi) ldsm_x4(afr[mi], sa + aOff + mi * 1280 + ks * 32);
#pragma unroll
            for (int ni = 0; ni < 4; ++ni) ldsm_x2(bfr[ni], sb2 + bOff + ni * 640 + ks * 32);
#pragma unroll
            for (int mi = 0; mi < 4; ++mi)
#pragma unroll
                for (int ni = 0; ni < 4; ++ni) mma16816(acc[mi][ni], afr[mi], bfr[ni]);
        }
        __syncthreads();
    }

    const int rl = lid >> 2;
    const int cl = 2 * (lid & 3);

    if constexpr (MODE == 4) {
        float* Ob = OF + sOb * b;
        const float* Xb = p5 + sOb * b;
#pragma unroll
        for (int mi = 0; mi < 4; ++mi)
#pragma unroll
            for (int half = 0; half < 2; ++half) {
                const int c = row0 + m_base + mi * 16 + rl + half * 8;
                const float inv = p1[c] * rsqrtf(p4[c] + BN_EPS);
                const float sh = (p0[c] - p3[c]) * inv + p2[c];
#pragma unroll
                for (int ni = 0; ni < 4; ++ni) {
                    const int cg = col0 + n_base + ni * 8 + cl;
                    float2 xv = *(const float2*)(Xb + (size_t)c * ldO + cg);
                    *(float2*)(Ob + (size_t)c * ldO + cg) = make_float2(
                        acc[mi][ni][2 * half + 0] * inv + sh + xv.x,
                        acc[mi][ni][2 * half + 1] * inv + sh + xv.y);
                }
            }
    } else { // MODE 5
        if (which == 0) {
            __nv_bfloat16* Ob = d_th2 + (size_t)b * NPIX * (2 * CI);
#pragma unroll
            for (int mi = 0; mi < 4; ++mi)
#pragma unroll
                for (int ni = 0; ni < 4; ++ni) {
                    const int cg = col0 + n_base + ni * 8 + cl;
#pragma unroll
                    for (int half = 0; half < 2; ++half) {
                        float v0 = acc[mi][ni][2 * half + 0] + p0[cg];
                        float v1 = acc[mi][ni][2 * half + 1] + p0[cg + 1];
                        __nv_bfloat16 h0 = __float2bfloat16_rn(v0);
                        __nv_bfloat16 h1 = __float2bfloat16_rn(v1);
                        __nv_bfloat16 l0 = __float2bfloat16_rn(v0 - __bfloat162float(h0));
                        __nv_bfloat16 l1 = __float2bfloat16_rn(v1 - __bfloat162float(h1));
                        const int rg = row0 + m_base + mi * 16 + rl + half * 8;
                        __nv_bfloat16* pr = Ob + (size_t)rg * (2 * CI) + cg;
                        *(uint32_t*)(pr)      = pack_bf2(h0, h1);
                        *(uint32_t*)(pr + CI) = pack_bf2(l0, l1);
                    }
                }
        } else {
            float* Ob = (which == 1 ? d_phiF : d_gF) + (size_t)b * NPIX * CI;
            const float* bias = (which == 1) ? p1 : p2;
#pragma unroll
            for (int mi = 0; mi < 4; ++mi) {
                const int rg = row0 + m_base + mi * 16 + rl;
#pragma unroll
                for (int ni = 0; ni < 4; ++ni) {
                    const int cg = col0 + n_base + ni * 8 + cl;
                    float bx = bias[cg], by = bias[cg + 1];
                    *(float2*)(Ob + (size_t)rg * CI + cg) =
                        make_float2(acc[mi][ni][0] + bx, acc[mi][ni][1] + by);
                    *(float2*)(Ob + (size_t)(rg + 8) * CI + cg) =
                        make_float2(acc[mi][ni][2] + bx, acc[mi][ni][3] + by);
                }
            }
        }
    }
}

// ============ flash kernel: S = th2*phiP2^T (3 passes), softmax, Y = P*g =======
#define FL_PITCH1 144
#define FL_PITCHP 272
#define FS_A    0
#define FS_B    (FS_A + 2 * 18432)
#define FS_PH   (FS_B + 2 * 18432)
#define FS_PL   (FS_PH + 34816)
#define FS_GH   (FS_PL + 34816)
#define FS_GL   (FS_GH + 34816)
#define FS_RED  (FS_GL + 34816)
#define FS_RMAX (FS_RED + 2048)
#define FS_RSUM (FS_RMAX + 512)
#define FS_RSC  (FS_RSUM + 512)
#define FS_RBC  (FS_RSC + 512)
#define FL_SMEM (FS_RBC + 512)

__global__ __launch_bounds__(256, 1) void flash_kernel()
{
    extern __shared__ __align__(16) char sm[];
    const uint32_t smb = smem_u32(sm);
    float* red  = (float*)(sm + FS_RED);
    float* rmax = (float*)(sm + FS_RMAX);
    float* rsum = (float*)(sm + FS_RSUM);
    float* rsc  = (float*)(sm + FS_RSC);
    float* rbc  = (float*)(sm + FS_RBC);

    const int tid = threadIdx.x, wid = tid >> 5, lid = tid & 31;
    const int b = blockIdx.y;
    const int n0 = blockIdx.x * 128;
    const int mrow = (wid & 1) * 64;
    const int ncol = (wid >> 1) * 32;
    const int rl = lid >> 2, cl = 2 * (lid & 3);

    const __nv_bfloat16* At = d_th2 + (size_t)b * NPIX * 256 + (size_t)n0 * 256;
    const __nv_bfloat16* Pt = d_phiP2 + (size_t)b * NPOOL * 256;
    const __nv_bfloat16* Gh = d_gPh + (size_t)b * CI * NPOOL;
    const __nv_bfloat16* Gl = d_gPl + (size_t)b * CI * NPOOL;

    if (tid < 128) { rmax[tid] = -1e30f; rsum[tid] = 0.f; }
    __syncthreads();

    const uint32_t a1 = (uint32_t)((mrow + (lid & 15)) * FL_PITCH1 + (lid >> 4) * 16);
    const uint32_t b1 = (uint32_t)((ncol + (lid & 7)) * FL_PITCH1 + ((lid >> 3) & 1) * 16);
    const uint32_t a2 = (uint32_t)((mrow + (lid & 15)) * FL_PITCHP + (lid >> 4) * 16);
    const uint32_t b2 = (uint32_t)((ncol + (lid & 7)) * FL_PITCHP + ((lid >> 3) & 1) * 16);

    float accY[4][4][4] = {};

    for (int mt = 0; mt < 8; ++mt) {
        const int m0 = mt * 128;

        // g tile loads (first commit group of this tile)
        {
            const uint32_t gh = smb + FS_GH, gl = smb + FS_GL;
#pragma unroll
            for (int t = 0; t < 8; ++t) {
                int j = tid + 256 * t;
                int row = j >> 4, seg = j & 15;
                uint32_t dst = (uint32_t)(row * FL_PITCHP + seg * 16);
                CP16(gh + dst, Gh + (size_t)row * NPOOL + m0 + seg * 8);
                CP16(gl + dst, Gl + (size_t)row * NPOOL + m0 + seg * 8);
            }
            CP_COMMIT();
        }

        // S-phase chunk: ch -> pass p = ch/2, kk = ch&1
        //   aK = (p==1?128:0)+kk*64, bK = (p==2?128:0)+kk*64
        auto issue1 = [&](int ch) {
            const int p = ch >> 1, kk = ch & 1;
            const int aK = (p == 1 ? 128 : 0) + kk * 64;
            const int bK = (p == 2 ? 128 : 0) + kk * 64;
            const uint32_t sa = smb + FS_A + (uint32_t)(ch & 1) * 18432;
            const uint32_t sbb = smb + FS_B + (uint32_t)(ch & 1) * 18432;
#pragma unroll
            for (int t = 0; t < 4; ++t) {
                int j = tid + 256 * t;
                int row = j >> 3, seg = j & 7;
                uint32_t dst = (uint32_t)(row * FL_PITCH1 + seg * 16);
                CP16(sa + dst, At + (size_t)row * 256 + aK + seg * 8);
                CP16(sbb + dst, Pt + (size_t)(m0 + row) * 256 + bK + seg * 8);
            }
            CP_COMMIT();
        };

        float accS[4][4][4] = {};
        issue1(0);
        for (int ch = 0; ch < 6; ++ch) {
            if (ch + 1 < 6) { issue1(ch + 1); CP_WAIT1(); }
            else CP_WAIT0();
            __syncthreads();
            const uint32_t sa = smb + FS_A + (uint32_t)(ch & 1) * 18432;
            const uint32_t sbb = smb + FS_B + (uint32_t)(ch & 1) * 18432;
#pragma unroll
            for (int ks = 0; ks < 4; ++ks) {
                uint32_t afr[4][4], bfr[4][2];
#pragma unroll
                for (int mi = 0; mi < 4; ++mi) ldsm_x4(afr[mi], sa + a1 + mi * 16 * FL_PITCH1 + ks * 32);
#pragma unroll
                for (int ni = 0; ni < 4; ++ni) ldsm_x2(bfr[ni], sbb + b1 + ni * 8 * FL_PITCH1 + ks * 32);
#pragma unroll
                for (int mi = 0; mi < 4; ++mi)
#pragma unroll
                    for (int ni = 0; ni < 4; ++ni) mma16816(accS[mi][ni], afr[mi], bfr[ni]);
            }
            __syncthreads();
        }

        // ---- online softmax ----
#pragma unroll
        for (int mi = 0; mi < 4; ++mi)
#pragma unroll
            for (int half = 0; half < 2; ++half) {
                float v = -1e30f;
#pragma unroll
                for (int ni = 0; ni < 4; ++ni)
                    v = fmaxf(v, fmaxf(accS[mi][ni][2 * half], accS[mi][ni][2 * half + 1]));
                v = fmaxf(v, __shfl_xor_sync(0xffffffffu, v, 1));
                v = fmaxf(v, __shfl_xor_sync(0xffffffffu, v, 2));
                if ((lid & 3) == 0)
                    red[(mrow + mi * 16 + rl + half * 8) * 4 + (wid >> 1)] = v;
            }
        __syncthreads();
        if (tid < 128) {
            float mOld = rmax[tid];
            float mNew = fmaxf(fmaxf(red[tid * 4], red[tid * 4 + 1]),
                               fmaxf(red[tid * 4 + 2], red[tid * 4 + 3]));
            mNew = fmaxf(mOld, mNew);
            rbc[tid] = mNew; rsc[tid] = __expf(mOld - mNew); rmax[tid] = mNew;
        }
        __syncthreads();
#pragma unroll
        for (int mi = 0; mi < 4; ++mi)
#pragma unroll
            for (int half = 0; half < 2; ++half) {
                const int r = mrow + mi * 16 + rl + half * 8;
                const float mb = rbc[r];
                const float sc = rsc[r];
                float s = 0.f;
#pragma unroll
                for (int ni = 0; ni < 4; ++ni) {
                    accY[mi][ni][2 * half]     *= sc;
                    accY[mi][ni][2 * half + 1] *= sc;
                    float e0 = __expf(accS[mi][ni][2 * half]     - mb);
                    float e1 = __expf(accS[mi][ni][2 * half + 1] - mb);
                    s += e0 + e1;
                    __nv_bfloat16 h0 = __float2bfloat16_rn(e0);
                    __nv_bfloat16 h1 = __float2bfloat16_rn(e1);
                    __nv_bfloat16 l0 = __float2bfloat16_rn(e0 - __bfloat162float(h0));
                    __nv_bfloat16 l1 = __float2bfloat16_rn(e1 - __bfloat162float(h1));
                    const uint32_t off = (uint32_t)(r * FL_PITCHP + (ncol + ni * 8 + cl) * 2);
                    *(uint32_t*)(sm + FS_PH + off) = pack_bf2(h0, h1);
                    *(uint32_t*)(sm + FS_PL + off) = pack_bf2(l0, l1);
                }
                s += __shfl_xor_sync(0xffffffffu, s, 1);
                s += __shfl_xor_sync(0xffffffffu, s, 2);
                if ((lid & 3) == 0) red[r * 4 + (wid >> 1)] = s;
            }
        __syncthreads();
        if (tid < 128)
            rsum[tid] = rsum[tid] * rsc[tid] +
                        (red[tid * 4] + red[tid * 4 + 1] + red[tid * 4 + 2] + red[tid * 4 + 3]);

        // ---- phase 2: Y += P_hi*g_hi + P_lo*g_hi + P_hi*g_lo ----
        const uint32_t pbuf[3] = { smb + FS_PH, smb + FS_PL, smb + FS_PH };
        const uint32_t gbuf[3] = { smb + FS_GH, smb + FS_GH, smb + FS_GL };
#pragma unroll
        for (int pass = 0; pass < 3; ++pass) {
            const uint32_t ab = pbuf[pass] + a2;
            const uint32_t bb = gbuf[pass] + b2;
#pragma unroll
            for (int ks = 0; ks < 8; ++ks) {
                uint32_t afr[4][4], bfr[4][2];
#pragma unroll
                for (int mi = 0; mi < 4; ++mi) ldsm_x4(afr[mi], ab + mi * 16 * FL_PITCHP + ks * 32);
#pragma unroll
                for (int ni = 0; ni < 4; ++ni) ldsm_x2(bfr[ni], bb + ni * 8 * FL_PITCHP + ks * 32);
#pragma unroll
                for (int mi = 0; mi < 4; ++mi)
#pragma unroll
                    for (int ni = 0; ni < 4; ++ni) mma16816(accY[mi][ni], afr[mi], bfr[ni]);
            }
        }
        __syncthreads();
    }

    // ---- epilogue: normalize, write y2 duo (hi|lo) ----
    __nv_bfloat16* Ob = d_y2 + (size_t)b * NPIX * 256 + (size_t)n0 * 256;
#pragma unroll
    for (int mi = 0; mi < 4; ++mi)
#pragma unroll
        for (int half = 0; half < 2; ++half) {
            const int r = mrow + mi * 16 + rl + half * 8;
            const float rinv = 1.f / rsum[r];
#pragma unroll
            for (int ni = 0; ni < 4; ++ni) {
                float v0 = accY[mi][ni][2 * half]     * rinv;
                float v1 = accY[mi][ni][2 * half + 1] * rinv;
                __nv_bfloat16 h0 = __float2bfloat16_rn(v0);
                __nv_bfloat16 h1 = __float2bfloat16_rn(v1);
                __nv_bfloat16 l0 = __float2bfloat16_rn(v0 - __bfloat162float(h0));
                __nv_bfloat16 l1 = __float2bfloat16_rn(v1 - __bfloat162float(h1));
                __nv_bfloat16* pr = Ob + (size_t)r * 256 + (ncol + ni * 8 + cl);
                *(uint32_t*)(pr)      = pack_bf2(h0, h1);
                *(uint32_t*)(pr + CI) = pack_bf2(l0, l1);
            }
        }
}

// ---------------- x transpose-convert: x[b][c][n] -> x2[b][n][hi|lo] -----------
__global__ __launch_bounds__(256) void conv_x_kernel(const float* __restrict__ x)
{
    __shared__ float t[32][33];
    const int b = blockIdx.z;
    const int c0 = blockIdx.y * 32, n0 = blockIdx.x * 32;
    const int tx = threadIdx.x, ty = threadIdx.y;
    const float* X = x + (size_t)b * CC * NPIX;
#pragma unroll
    for (int i = 0; i < 4; ++i)
        t[ty + 8 * i][tx] = X[(size_t)(c0 + ty + 8 * i) * NPIX + n0 + tx];
    __syncthreads();
    __nv_bfloat16* O = d_x2 + (size_t)b * NPIX * (2 * CC);
#pragma unroll
    for (int i = 0; i < 4; ++i) {
        int n = n0 + ty + 8 * i;
        float v = t[tx][ty + 8 * i];
        __nv_bfloat16 h = __float2bfloat16_rn(v);
        __nv_bfloat16 l = __float2bfloat16_rn(v - __bfloat162float(h));
        __nv_bfloat16* row = O + (size_t)n * (2 * CC) + c0 + tx;
        row[0] = h; row[CC] = l;
    }
}

// ---------------- merged weight convert (all 4 weights, one launch) -------------
__global__ void conv_w_all(const float* __restrict__ th_w, const float* __restrict__ ph_w,
                           const float* __restrict__ g_w, const float* __restrict__ W_w)
{
    const int which = blockIdx.y;
    const float* src = which == 0 ? th_w : which == 1 ? ph_w : which == 2 ? g_w : W_w;
    const int K = (which < 3) ? CC : CI;   // both layouts have 32768 elements
    __nv_bfloat16* dst = (which < 3) ? d_w2all + (size_t)which * CI * (2 * CC) : d_Ww2;

    int idx = blockIdx.x * 256 + threadIdx.x;
    if (idx >= CI * CC) return;
    int r = idx / K, k = idx - r * K;
    float v = src[idx];
    __nv_bfloat16 h = __float2bfloat16_rn(v);
    __nv_bfloat16 l = __float2bfloat16_rn(v - __bfloat162float(h));
    __nv_bfloat16* row = dst + (size_t)r * 2 * K;
    row[k] = h;
    row[K + k] = l;
}

// ---------------- pool -----------------------------------------------------------
__global__ __launch_bounds__(128) void pool_kernel()
{
    const int m = blockIdx.x & (NPOOL - 1);
    const int b = blockIdx.x >> 10;
    const int ci = threadIdx.x;
    const int ph = m >> 5, pw = m & 31;
    const int n00 = (2 * ph) * WD + 2 * pw;
    const size_t base = ((size_t)b * NPIX + n00) * CI + ci;

    float p = fmaxf(fmaxf(d_phiF[base], d_phiF[base + CI]),
                    fmaxf(d_phiF[base + (size_t)WD * CI], d_phiF[base + (size_t)(WD + 1) * CI]));
    __nv_bfloat16 h = __float2bfloat16_rn(p);
    __nv_bfloat16 l = __float2bfloat16_rn(p - __bfloat162float(h));
    __nv_bfloat16* prow = d_phiP2 + ((size_t)b * NPOOL + m) * (2 * CI);
    prow[ci] = h; prow[CI + ci] = l;

    float g = fmaxf(fmaxf(d_gF[base], d_gF[base + CI]),
                    fmaxf(d_gF[base + (size_t)WD * CI], d_gF[base + (size_t)(WD + 1) * CI]));
    __nv_bfloat16 gh = __float2bfloat16_rn(g);
    __nv_bfloat16 gl = __float2bfloat16_rn(g - __bfloat162float(gh));
    d_gPh[((size_t)b * CI + ci) * NPOOL + m] = gh;
    d_gPl[((size_t)b * CI + ci) * NPOOL + m] = gl;
}

// ---------------- launch ----------------------------------------------------------
template <typename T>
static T* sym_addr(const void* sym)
{
    void* p = nullptr;
    cudaGetSymbolAddress(&p, sym);
    return (T*)p;
}

extern "C" void kernel_launch(void* const* d_in, const int* in_sizes, int n_in,
                              void* d_out, int out_size)
{
    const float* x    = (const float*)d_in[0];
    const float* g_w  = (const float*)d_in[1];
    const float* g_b  = (const float*)d_in[2];
    const float* th_w = (const float*)d_in[3];
    const float* th_b = (const float*)d_in[4];
    const float* ph_w = (const float*)d_in[5];
    const float* ph_b = (const float*)d_in[6];
    const float* W_w  = (const float*)d_in[7];
    const float* W_b  = (const float*)d_in[8];
    const float* gam  = (const float*)d_in[9];
    const float* bet  = (const float*)d_in[10];
    const float* mea  = (const float*)d_in[11];
    const float* var  = (const float*)d_in[12];
    float* out = (float*)d_out;

    __nv_bfloat16* x2    = sym_addr<__nv_bfloat16>(d_x2);
    __nv_bfloat16* w2all = sym_addr<__nv_bfloat16>(d_w2all);
    __nv_bfloat16* Ww2   = sym_addr<__nv_bfloat16>(d_Ww2);
    __nv_bfloat16* y2    = sym_addr<__nv_bfloat16>(d_y2);

    cudaFuncSetAttribute(flash_kernel, cudaFuncAttributeMaxDynamicSharedMemorySize, FL_SMEM);

    conv_x_kernel<<<dim3(NPIX / 32, CC / 32, BB), dim3(32, 8)>>>(x);
    conv_w_all<<<dim3((CI * CC + 255) / 256, 4), 256>>>(th_w, ph_w, g_w, W_w);

    // merged projections: z = which*8 + b; K base 256 (hi|lo), 3 passes
    mma_gemm<5, 256><<<dim3(1, 32, 24), 256>>>(
        x2, w2all, (size_t)NPIX * 512, (size_t)CI * 512,
        nullptr, 0, 0, th_b, ph_b, g_b, nullptr, nullptr, nullptr);

    pool_kernel<<<BB * NPOOL, 128>>>();

    flash_kernel<<<dim3(NPIX / 128, BB), 256, FL_SMEM>>>();

    // out GEMM: A=Ww2 [c][hi|lo], B=y2 [n][hi|lo], K base 128, 3 passes
    mma_gemm<4, 128><<<dim3(NPIX / 128, CC / 128, BB), 256>>>(
        Ww2, y2, 0, (size_t)NPIX * 256,
        out, (size_t)CC * NPIX, NPIX, W_b, gam, bet, mea, var, x);
}

// round 7
// speedup vs baseline: 2.1759x; 1.0577x over previous
#include <cuda_runtime.h>
#include <cuda_bf16.h>
#include <math.h>
#include <stdint.h>

#define BB 8
#define CC 256
#define CI 128
#define NPIX 4096
#define NPOOL 1024
#define WD 64
#define BN_EPS 1e-5f

// ---------------- scratch (__device__ globals, no allocations) ----------------
__device__ __align__(16) __nv_bfloat16 d_x2  [(size_t)BB * NPIX * (2 * CC)];  // [b][n][hi|lo]
__device__ __align__(16) __nv_bfloat16 d_w2all[(size_t)3 * CI * 2 * CC];      // theta|phi|g: [ci][hi|lo]
__device__ __align__(16) __nv_bfloat16 d_Ww2 [(size_t)CC * 2 * CI];           // [c][hi|lo]
__device__ __align__(16) __nv_bfloat16 d_th2 [(size_t)BB * NPIX * (2 * CI)];  // [b][n][hi|lo]
__device__ __align__(16) __nv_bfloat16 d_phiP2[(size_t)BB * NPOOL * (2 * CI)];// [b][m][hi|lo]
__device__ __align__(16) __nv_bfloat16 d_gPh [(size_t)BB * CI * NPOOL];       // [b][ci][m] hi
__device__ __align__(16) __nv_bfloat16 d_gPl [(size_t)BB * CI * NPOOL];       // [b][ci][m] lo
__device__ __align__(16) __nv_bfloat16 d_y2  [(size_t)BB * NPIX * (2 * CI)];  // [b][n][hi|lo]

// ---------------- helpers -------------------------------------------------------
__device__ __forceinline__ uint32_t smem_u32(const void* p) {
    uint32_t a;
    asm("{ .reg .u64 t; cvta.to.shared.u64 t, %1; cvt.u32.u64 %0, t; }" : "=r"(a) : "l"(p));
    return a;
}
__device__ __forceinline__ uint32_t pack_bf2(__nv_bfloat16 a, __nv_bfloat16 b) {
    __nv_bfloat162 h(a, b);
    return *(uint32_t*)&h;
}
#define CP16(dst, src) asm volatile("cp.async.ca.shared.global [%0], [%1], 16;" :: "r"(dst), "l"(src))
#define CP_COMMIT()    asm volatile("cp.async.commit_group;" ::: "memory")
#define CP_WAIT1()     asm volatile("cp.async.wait_group 1;" ::: "memory")
#define CP_WAIT0()     asm volatile("cp.async.wait_group 0;" ::: "memory")

__device__ __forceinline__ void ldsm_x4(uint32_t* r, uint32_t addr) {
    asm volatile("ldmatrix.sync.aligned.m8n8.x4.shared.b16 {%0,%1,%2,%3}, [%4];"
                 : "=r"(r[0]), "=r"(r[1]), "=r"(r[2]), "=r"(r[3]) : "r"(addr));
}
__device__ __forceinline__ void ldsm_x2(uint32_t* r, uint32_t addr) {
    asm volatile("ldmatrix.sync.aligned.m8n8.x2.shared.b16 {%0,%1}, [%2];"
                 : "=r"(r[0]), "=r"(r[1]) : "r"(addr));
}
__device__ __forceinline__ void mma16816(float* c, const uint32_t* a, const uint32_t* b) {
    asm volatile("mma.sync.aligned.m16n8k16.row.col.f32.bf16.bf16.f32 "
                 "{%0,%1,%2,%3}, {%4,%5,%6,%7}, {%8,%9}, {%0,%1,%2,%3};"
                 : "+f"(c[0]), "+f"(c[1]), "+f"(c[2]), "+f"(c[3])
                 : "r"(a[0]), "r"(a[1]), "r"(a[2]), "r"(a[3]), "r"(b[0]), "r"(b[1]));
}

// ============ generic warp-mma GEMM with split-pass K slices =====================
// D = A_hi*B_hi + A_lo*B_hi + A_hi*B_lo over 3 passes; ch -> (pass, kk):
//   aK = (p==1?KB:0)+kk*32, bK = (p==2?KB:0)+kk*32.  nchunks = 3*KB/32.
#define STG_BYTES 20480
#define SB_OFF    10240

// MODE 4: fp32 out + BN(row) + residual (p0=Wb p1=gamma p2=beta p3=mean p4=var p5=x)
// MODE 5: merged projections; blockIdx.z = which*8 + b.
//         which0: duo->d_th2 (+p0)
//         which1: fused 2x2 maxpool + bias(p1) -> d_phiP2 duo
//         which2: fused 2x2 maxpool + bias(p2) -> d_gPh/d_gPl
template <int MODE, int KB>
__global__ __launch_bounds__(256) void mma_gemm(
    const __nv_bfloat16* __restrict__ A, const __nv_bfloat16* __restrict__ B,
    size_t sAb, size_t sBb,
    float* OF, size_t sOb, int ldO,
    const float* __restrict__ p0, const float* __restrict__ p1,
    const float* __restrict__ p2, const float* __restrict__ p3,
    const float* __restrict__ p4, const float* __restrict__ p5)
{
    constexpr int ldK = 2 * KB;
    constexpr int k32pp = KB / 32;
    constexpr int nchunks = 3 * k32pp;

    __shared__ __align__(16) char sm[2 * STG_BYTES];
    const uint32_t smb = smem_u32(sm);
    const int tid = threadIdx.x;
    const int wid = tid >> 5, lid = tid & 31;
    const int b = (MODE == 5) ? (blockIdx.z & 7) : blockIdx.z;
    const int which = (MODE == 5) ? (blockIdx.z >> 3) : 0;
    const int row0 = blockIdx.y * 128, col0 = blockIdx.x * 128;
    const int m_base = (wid & 1) * 64;
    const int n_base = (wid >> 1) * 32;

    const __nv_bfloat16* At = A + sAb * b + (size_t)row0 * ldK;
    const __nv_bfloat16* Bt = B + sBb * (size_t)((MODE == 5) ? which : b) + (size_t)col0 * ldK;

    const int r0i = tid >> 2, s0 = (tid & 3);
    const int r1i = (tid + 256) >> 2;
    const uint32_t d0 = (uint32_t)(r0i * 80 + s0 * 16);
    const uint32_t d1 = (uint32_t)(r1i * 80 + s0 * 16);
    const uint32_t aOff = (uint32_t)((m_base + (lid & 15)) * 80 + (lid >> 4) * 16);
    const uint32_t bOff = (uint32_t)((n_base + (lid & 7)) * 80 + ((lid >> 3) & 1) * 16);

    float acc[4][4][4] = {};

    auto issue = [&](int ch) {
        const int p = ch / k32pp, kk = ch - p * k32pp;
        const int aK = (p == 1 ? KB : 0) + kk * 32;
        const int bK = (p == 2 ? KB : 0) + kk * 32;
        const uint32_t sa = smb + (uint32_t)(ch & 1) * STG_BYTES;
        const uint32_t sb2 = sa + SB_OFF;
        const __nv_bfloat16* ga = At + aK;
        const __nv_bfloat16* gb = Bt + bK;
        CP16(sa + d0, ga + (size_t)r0i * ldK + s0 * 8);
        CP16(sa + d1, ga + (size_t)r1i * ldK + s0 * 8);
        CP16(sb2 + d0, gb + (size_t)r0i * ldK + s0 * 8);
        CP16(sb2 + d1, gb + (size_t)r1i * ldK + s0 * 8);
    };

    issue(0);
    CP_COMMIT();
    for (int ch = 0; ch < nchunks; ++ch) {
        if (ch + 1 < nchunks) { issue(ch + 1); CP_COMMIT(); CP_WAIT1(); }
        else CP_WAIT0();
        __syncthreads();
        const uint32_t sa = smb + (uint32_t)(ch & 1) * STG_BYTES;
        const uint32_t sb2 = sa + SB_OFF;
#pragma unroll
        for (int ks = 0; ks < 2; ++ks) {
            uint32_t afr[4][4], bfr[4][2];
#pragma unroll
            for (int mi = 0; mi < 4; ++mi) ldsm_x4(afr[mi], sa + aOff + mi * 1280 + ks * 32);
#pragma unroll
            for (int ni = 0; ni < 4; ++ni) ldsm_x2(bfr[ni], sb2 + bOff + ni * 640 + ks * 32);
#pragma unroll
            for (int mi = 0; mi < 4; ++mi)
#pragma unroll
                for (int ni = 0; ni < 4; ++ni) mma16816(acc[mi][ni], afr[mi], bfr[ni]);
        }
        __syncthreads();
    }

    const int rl = lid >> 2;
    const int cl = 2 * (lid & 3);

    if constexpr (MODE == 4) {
        float* Ob = OF + sOb * b;
        const float* Xb = p5 + sOb * b;
#pragma unroll
        for (int mi = 0; mi < 4; ++mi)
#pragma unroll
            for (int half = 0; half < 2; ++half) {
                const int c = row0 + m_base + mi * 16 + rl + half * 8;
                const float inv = p1[c] * rsqrtf(p4[c] + BN_EPS);
                const float sh = (p0[c] - p3[c]) * inv + p2[c];
#pragma unroll
                for (int ni = 0; ni < 4; ++ni) {
                    const int cg = col0 + n_base + ni * 8 + cl;
                    float2 xv = *(const float2*)(Xb + (size_t)c * ldO + cg);
                    *(float2*)(Ob + (size_t)c * ldO + cg) = make_float2(
                        acc[mi][ni][2 * half + 0] * inv + sh + xv.x,
                        acc[mi][ni][2 * half + 1] * inv + sh + xv.y);
                }
            }
    } else { // MODE 5
        if (which == 0) {
            __nv_bfloat16* Ob = d_th2 + (size_t)b * NPIX * (2 * CI);
#pragma unroll
            for (int mi = 0; mi < 4; ++mi)
#pragma unroll
                for (int ni = 0; ni < 4; ++ni) {
                    const int cg = col0 + n_base + ni * 8 + cl;
#pragma unroll
                    for (int half = 0; half < 2; ++half) {
                        float v0 = acc[mi][ni][2 * half + 0] + p0[cg];
                        float v1 = acc[mi][ni][2 * half + 1] + p0[cg + 1];
                        __nv_bfloat16 h0 = __float2bfloat16_rn(v0);
                        __nv_bfloat16 h1 = __float2bfloat16_rn(v1);
                        __nv_bfloat16 l0 = __float2bfloat16_rn(v0 - __bfloat162float(h0));
                        __nv_bfloat16 l1 = __float2bfloat16_rn(v1 - __bfloat162float(h1));
                        const int rg = row0 + m_base + mi * 16 + rl + half * 8;
                        __nv_bfloat16* pr = Ob + (size_t)rg * (2 * CI) + cg;
                        *(uint32_t*)(pr)      = pack_bf2(h0, h1);
                        *(uint32_t*)(pr + CI) = pack_bf2(l0, l1);
                    }
                }
        } else {
            // Fused 2x2 maxpool epilogue. Tile rows row0..row0+127 cover image
            // rows {2t, 2t+1} (t = blockIdx.y), so pool windows are tile-local:
            // window rows within tile = {2pw, 2pw+1, 64+2pw, 65+2pw}.
            float (*stage)[33] = (float(*)[33])sm;
            const float* bias = (which == 1) ? p1 : p2;
            const int t_band = blockIdx.y;
#pragma unroll 1
            for (int cg2 = 0; cg2 < 4; ++cg2) {
                __syncthreads();
                if ((wid >> 1) == cg2) {
#pragma unroll
                    for (int mi = 0; mi < 4; ++mi)
#pragma unroll
                        for (int ni = 0; ni < 4; ++ni) {
                            const int r = m_base + mi * 16 + rl;
                            const int c = ni * 8 + cl;
                            stage[r][c]     = acc[mi][ni][0];
                            stage[r][c + 1] = acc[mi][ni][1];
                            stage[r + 8][c]     = acc[mi][ni][2];
                            stage[r + 8][c + 1] = acc[mi][ni][3];
                        }
                }
                __syncthreads();
                if (which == 1) { // phi: duo rows [m][hi|lo]; ci fastest across threads
                    const int c = tid & 31, pw0 = (tid >> 5) * 4;
                    const int ci = cg2 * 32 + c;
#pragma unroll
                    for (int j = 0; j < 4; ++j) {
                        const int pw = pw0 + j;
                        float v = fmaxf(fmaxf(stage[2 * pw][c], stage[2 * pw + 1][c]),
                                        fmaxf(stage[2 * pw + 64][c], stage[2 * pw + 65][c]))
                                  + bias[ci];
                        __nv_bfloat16 h = __float2bfloat16_rn(v);
                        __nv_bfloat16 l = __float2bfloat16_rn(v - __bfloat162float(h));
                        const int m = t_band * 32 + pw;
                        __nv_bfloat16* pr = d_phiP2 + ((size_t)b * NPOOL + m) * (2 * CI);
                        pr[ci] = h; pr[CI + ci] = l;
                    }
                } else {          // g: [ci][m] planes; m fastest across threads
                    const int pw = tid & 31, c0v = (tid >> 5) * 4;
                    const int m = t_band * 32 + pw;
#pragma unroll
                    for (int j = 0; j < 4; ++j) {
                        const int c = c0v + j, ci = cg2 * 32 + c;
                        float v = fmaxf(fmaxf(stage[2 * pw][c], stage[2 * pw + 1][c]),
                                        fmaxf(stage[2 * pw + 64][c], stage[2 * pw + 65][c]))
                                  + bias[ci];
                        __nv_bfloat16 h = __float2bfloat16_rn(v);
                        __nv_bfloat16 l = __float2bfloat16_rn(v - __bfloat162float(h));
                        d_gPh[((size_t)b * CI + ci) * NPOOL + m] = h;
                        d_gPl[((size_t)b * CI + ci) * NPOOL + m] = l;
                    }
                }
            }
        }
    }
}

// ============ flash kernel: S = th2*phiP2^T (3 passes), softmax, Y = P*g =======
#define FL_PITCH1 144
#define FL_PITCHP 272
#define FS_A    0
#define FS_B    (FS_A + 2 * 18432)
#define FS_PH   (FS_B + 2 * 18432)
#define FS_PL   (FS_PH + 34816)
#define FS_GH   (FS_PL + 34816)
#define FS_GL   (FS_GH + 34816)
#define FS_RED  (FS_GL + 34816)
#define FS_RMAX (FS_RED + 2048)
#define FS_RSUM (FS_RMAX + 512)
#define FS_RSC  (FS_RSUM + 512)
#define FS_RBC  (FS_RSC + 512)
#define FL_SMEM (FS_RBC + 512)

__global__ __launch_bounds__(256, 1) void flash_kernel()
{
    extern __shared__ __align__(16) char sm[];
    const uint32_t smb = smem_u32(sm);
    float* red  = (float*)(sm + FS_RED);
    float* rmax = (float*)(sm + FS_RMAX);
    float* rsum = (float*)(sm + FS_RSUM);
    float* rsc  = (float*)(sm + FS_RSC);
    float* rbc  = (float*)(sm + FS_RBC);

    const int tid = threadIdx.x, wid = tid >> 5, lid = tid & 31;
    const int b = blockIdx.y;
    const int n0 = blockIdx.x * 128;
    const int mrow = (wid & 1) * 64;
    const int ncol = (wid >> 1) * 32;
    const int rl = lid >> 2, cl = 2 * (lid & 3);

    const __nv_bfloat16* At = d_th2 + (size_t)b * NPIX * 256 + (size_t)n0 * 256;
    const __nv_bfloat16* Pt = d_phiP2 + (size_t)b * NPOOL * 256;
    const __nv_bfloat16* Gh = d_gPh + (size_t)b * CI * NPOOL;
    const __nv_bfloat16* Gl = d_gPl + (size_t)b * CI * NPOOL;

    if (tid < 128) { rmax[tid] = -1e30f; rsum[tid] = 0.f; }
    __syncthreads();

    const uint32_t a1 = (uint32_t)((mrow + (lid & 15)) * FL_PITCH1 + (lid >> 4) * 16);
    const uint32_t b1 = (uint32_t)((ncol + (lid & 7)) * FL_PITCH1 + ((lid >> 3) & 1) * 16);
    const uint32_t a2 = (uint32_t)((mrow + (lid & 15)) * FL_PITCHP + (lid >> 4) * 16);
    const uint32_t b2 = (uint32_t)((ncol + (lid & 7)) * FL_PITCHP + ((lid >> 3) & 1) * 16);

    float accY[4][4][4] = {};

    for (int mt = 0; mt < 8; ++mt) {
        const int m0 = mt * 128;

        {
            const uint32_t gh = smb + FS_GH, gl = smb + FS_GL;
#pragma unroll
            for (int t = 0; t < 8; ++t) {
                int j = tid + 256 * t;
                int row = j >> 4, seg = j & 15;
                uint32_t dst = (uint32_t)(row * FL_PITCHP + seg * 16);
                CP16(gh + dst, Gh + (size_t)row * NPOOL + m0 + seg * 8);
                CP16(gl + dst, Gl + (size_t)row * NPOOL + m0 + seg * 8);
            }
            CP_COMMIT();
        }

        auto issue1 = [&](int ch) {
            const int p = ch >> 1, kk = ch & 1;
            const int aK = (p == 1 ? 128 : 0) + kk * 64;
            const int bK = (p == 2 ? 128 : 0) + kk * 64;
            const uint32_t sa = smb + FS_A + (uint32_t)(ch & 1) * 18432;
            const uint32_t sbb = smb + FS_B + (uint32_t)(ch & 1) * 18432;
#pragma unroll
            for (int t = 0; t < 4; ++t) {
                int j = tid + 256 * t;
                int row = j >> 3, seg = j & 7;
                uint32_t dst = (uint32_t)(row * FL_PITCH1 + seg * 16);
                CP16(sa + dst, At + (size_t)row * 256 + aK + seg * 8);
                CP16(sbb + dst, Pt + (size_t)(m0 + row) * 256 + bK + seg * 8);
            }
            CP_COMMIT();
        };

        float accS[4][4][4] = {};
        issue1(0);
        for (int ch = 0; ch < 6; ++ch) {
            if (ch + 1 < 6) { issue1(ch + 1); CP_WAIT1(); }
            else CP_WAIT0();
            __syncthreads();
            const uint32_t sa = smb + FS_A + (uint32_t)(ch & 1) * 18432;
            const uint32_t sbb = smb + FS_B + (uint32_t)(ch & 1) * 18432;
#pragma unroll
            for (int ks = 0; ks < 4; ++ks) {
                uint32_t afr[4][4], bfr[4][2];
#pragma unroll
                for (int mi = 0; mi < 4; ++mi) ldsm_x4(afr[mi], sa + a1 + mi * 16 * FL_PITCH1 + ks * 32);
#pragma unroll
                for (int ni = 0; ni < 4; ++ni) ldsm_x2(bfr[ni], sbb + b1 + ni * 8 * FL_PITCH1 + ks * 32);
#pragma unroll
                for (int mi = 0; mi < 4; ++mi)
#pragma unroll
                    for (int ni = 0; ni < 4; ++ni) mma16816(accS[mi][ni], afr[mi], bfr[ni]);
            }
            __syncthreads();
        }

        // ---- online softmax ----
#pragma unroll
        for (int mi = 0; mi < 4; ++mi)
#pragma unroll
            for (int half = 0; half < 2; ++half) {
                float v = -1e30f;
#pragma unroll
                for (int ni = 0; ni < 4; ++ni)
                    v = fmaxf(v, fmaxf(accS[mi][ni][2 * half], accS[mi][ni][2 * half + 1]));
                v = fmaxf(v, __shfl_xor_sync(0xffffffffu, v, 1));
                v = fmaxf(v, __shfl_xor_sync(0xffffffffu, v, 2));
                if ((lid & 3) == 0)
                    red[(mrow + mi * 16 + rl + half * 8) * 4 + (wid >> 1)] = v;
            }
        __syncthreads();
        if (tid < 128) {
            float mOld = rmax[tid];
            float mNew = fmaxf(fmaxf(red[tid * 4], red[tid * 4 + 1]),
                               fmaxf(red[tid * 4 + 2], red[tid * 4 + 3]));
            mNew = fmaxf(mOld, mNew);
            rbc[tid] = mNew; rsc[tid] = __expf(mOld - mNew); rmax[tid] = mNew;
        }
        __syncthreads();
#pragma unroll
        for (int mi = 0; mi < 4; ++mi)
#pragma unroll
            for (int half = 0; half < 2; ++half) {
                const int r = mrow + mi * 16 + rl + half * 8;
                const float mb = rbc[r];
                const float sc = rsc[r];
                float s = 0.f;
#pragma unroll
                for (int ni = 0; ni < 4; ++ni) {
                    accY[mi][ni][2 * half]     *= sc;
                    accY[mi][ni][2 * half + 1] *= sc;
                    float e0 = __expf(accS[mi][ni][2 * half]     - mb);
                    float e1 = __expf(accS[mi][ni][2 * half + 1] - mb);
                    s += e0 + e1;
                    __nv_bfloat16 h0 = __float2bfloat16_rn(e0);
                    __nv_bfloat16 h1 = __float2bfloat16_rn(e1);
                    __nv_bfloat16 l0 = __float2bfloat16_rn(e0 - __bfloat162float(h0));
                    __nv_bfloat16 l1 = __float2bfloat16_rn(e1 - __bfloat162float(h1));
                    const uint32_t off = (uint32_t)(r * FL_PITCHP + (ncol + ni * 8 + cl) * 2);
                    *(uint32_t*)(sm + FS_PH + off) = pack_bf2(h0, h1);
                    *(uint32_t*)(sm + FS_PL + off) = pack_bf2(l0, l1);
                }
                s += __shfl_xor_sync(0xffffffffu, s, 1);
                s += __shfl_xor_sync(0xffffffffu, s, 2);
                if ((lid & 3) == 0) red[r * 4 + (wid >> 1)] = s;
            }
        __syncthreads();
        if (tid < 128)
            rsum[tid] = rsum[tid] * rsc[tid] +
                        (red[tid * 4] + red[tid * 4 + 1] + red[tid * 4 + 2] + red[tid * 4 + 3]);

        // ---- phase 2: Y += P_hi*g_hi + P_lo*g_hi + P_hi*g_lo ----
        const uint32_t pbuf[3] = { smb + FS_PH, smb + FS_PL, smb + FS_PH };
        const uint32_t gbuf[3] = { smb + FS_GH, smb + FS_GH, smb + FS_GL };
#pragma unroll
        for (int pass = 0; pass < 3; ++pass) {
            const uint32_t ab = pbuf[pass] + a2;
            const uint32_t bb = gbuf[pass] + b2;
#pragma unroll
            for (int ks = 0; ks < 8; ++ks) {
                uint32_t afr[4][4], bfr[4][2];
#pragma unroll
                for (int mi = 0; mi < 4; ++mi) ldsm_x4(afr[mi], ab + mi * 16 * FL_PITCHP + ks * 32);
#pragma unroll
                for (int ni = 0; ni < 4; ++ni) ldsm_x2(bfr[ni], bb + ni * 8 * FL_PITCHP + ks * 32);
#pragma unroll
                for (int mi = 0; mi < 4; ++mi)
#pragma unroll
                    for (int ni = 0; ni < 4; ++ni) mma16816(accY[mi][ni], afr[mi], bfr[ni]);
            }
        }
        __syncthreads();
    }

    // ---- epilogue: normalize, write y2 duo (hi|lo) ----
    __nv_bfloat16* Ob = d_y2 + (size_t)b * NPIX * 256 + (size_t)n0 * 256;
#pragma unroll
    for (int mi = 0; mi < 4; ++mi)
#pragma unroll
        for (int half = 0; half < 2; ++half) {
            const int r = mrow + mi * 16 + rl + half * 8;
            const float rinv = 1.f / rsum[r];
#pragma unroll
            for (int ni = 0; ni < 4; ++ni) {
                float v0 = accY[mi][ni][2 * half]     * rinv;
                float v1 = accY[mi][ni][2 * half + 1] * rinv;
                __nv_bfloat16 h0 = __float2bfloat16_rn(v0);
                __nv_bfloat16 h1 = __float2bfloat16_rn(v1);
                __nv_bfloat16 l0 = __float2bfloat16_rn(v0 - __bfloat162float(h0));
                __nv_bfloat16 l1 = __float2bfloat16_rn(v1 - __bfloat162float(h1));
                __nv_bfloat16* pr = Ob + (size_t)r * 256 + (ncol + ni * 8 + cl);
                *(uint32_t*)(pr)      = pack_bf2(h0, h1);
                *(uint32_t*)(pr + CI) = pack_bf2(l0, l1);
            }
        }
}

// ---------------- x transpose-convert: x[b][c][n] -> x2[b][n][hi|lo] -----------
__global__ __launch_bounds__(256) void conv_x_kernel(const float* __restrict__ x)
{
    __shared__ float t[32][33];
    const int b = blockIdx.z;
    const int c0 = blockIdx.y * 32, n0 = blockIdx.x * 32;
    const int tx = threadIdx.x, ty = threadIdx.y;
    const float* X = x + (size_t)b * CC * NPIX;
#pragma unroll
    for (int i = 0; i < 4; ++i)
        t[ty + 8 * i][tx] = X[(size_t)(c0 + ty + 8 * i) * NPIX + n0 + tx];
    __syncthreads();
    __nv_bfloat16* O = d_x2 + (size_t)b * NPIX * (2 * CC);
#pragma unroll
    for (int i = 0; i < 4; ++i) {
        int n = n0 + ty + 8 * i;
        float v = t[tx][ty + 8 * i];
        __nv_bfloat16 h = __float2bfloat16_rn(v);
        __nv_bfloat16 l = __float2bfloat16_rn(v - __bfloat162float(h));
        __nv_bfloat16* row = O + (size_t)n * (2 * CC) + c0 + tx;
        row[0] = h; row[CC] = l;
    }
}

// ---------------- merged weight convert (all 4 weights, one launch) -------------
__global__ void conv_w_all(const float* __restrict__ th_w, const float* __restrict__ ph_w,
                           const float* __restrict__ g_w, const float* __restrict__ W_w)
{
    const int which = blockIdx.y;
    const float* src = which == 0 ? th_w : which == 1 ? ph_w : which == 2 ? g_w : W_w;
    const int K = (which < 3) ? CC : CI;
    __nv_bfloat16* dst = (which < 3) ? d_w2all + (size_t)which * CI * (2 * CC) : d_Ww2;

    int idx = blockIdx.x * 256 + threadIdx.x;
    if (idx >= CI * CC) return;
    int r = idx / K, k = idx - r * K;
    float v = src[idx];
    __nv_bfloat16 h = __float2bfloat16_rn(v);
    __nv_bfloat16 l = __float2bfloat16_rn(v - __bfloat162float(h));
    __nv_bfloat16* row = dst + (size_t)r * 2 * K;
    row[k] = h;
    row[K + k] = l;
}

// ---------------- launch ----------------------------------------------------------
template <typename T>
static T* sym_addr(const void* sym)
{
    void* p = nullptr;
    cudaGetSymbolAddress(&p, sym);
    return (T*)p;
}

extern "C" void kernel_launch(void* const* d_in, const int* in_sizes, int n_in,
                              void* d_out, int out_size)
{
    const float* x    = (const float*)d_in[0];
    const float* g_w  = (const float*)d_in[1];
    const float* g_b  = (const float*)d_in[2];
    const float* th_w = (const float*)d_in[3];
    const float* th_b = (const float*)d_in[4];
    const float* ph_w = (const float*)d_in[5];
    const float* ph_b = (const float*)d_in[6];
    const float* W_w  = (const float*)d_in[7];
    const float* W_b  = (const float*)d_in[8];
    const float* gam  = (const float*)d_in[9];
    const float* bet  = (const float*)d_in[10];
    const float* mea  = (const float*)d_in[11];
    const float* var  = (const float*)d_in[12];
    float* out = (float*)d_out;

    __nv_bfloat16* x2    = sym_addr<__nv_bfloat16>(d_x2);
    __nv_bfloat16* w2all = sym_addr<__nv_bfloat16>(d_w2all);
    __nv_bfloat16* Ww2   = sym_addr<__nv_bfloat16>(d_Ww2);
    __nv_bfloat16* y2    = sym_addr<__nv_bfloat16>(d_y2);

    cudaFuncSetAttribute(flash_kernel, cudaFuncAttributeMaxDynamicSharedMemorySize, FL_SMEM);

    conv_x_kernel<<<dim3(NPIX / 32, CC / 32, BB), dim3(32, 8)>>>(x);
    conv_w_all<<<dim3((CI * CC + 255) / 256, 4), 256>>>(th_w, ph_w, g_w, W_w);

    // merged projections with fused pool for phi/g: z = which*8 + b
    mma_gemm<5, 256><<<dim3(1, 32, 24), 256>>>(
        x2, w2all, (size_t)NPIX * 512, (size_t)CI * 512,
        nullptr, 0, 0, th_b, ph_b, g_b, nullptr, nullptr, nullptr);

    flash_kernel<<<dim3(NPIX / 128, BB), 256, FL_SMEM>>>();

    // out GEMM: A=Ww2 [c][hi|lo], B=y2 [n][hi|lo], K base 128, 3 passes
    mma_gemm<4, 128><<<dim3(NPIX / 128, CC / 128, BB), 256>>>(
        Ww2, y2, 0, (size_t)NPIX * 256,
        out, (size_t)CC * NPIX, NPIX, W_b, gam, bet, mea, var, x);
}